// round 14
// baseline (speedup 1.0000x reference)
#include <cuda_runtime.h>
#include <cuda_bf16.h>
#include <cstdint>

#define TTT_LR  0.01f
#define KSIZE   5

// NT tiling: 128x128x64, 8 warps of 64x32, occ 2
#define BK 64
#define NPITCH 144
#define NA_SZ (128 * NPITCH)
#define NST (2 * NA_SZ)
#define STAGES 3
#define SMEM_NT (STAGES * NST)        // 110592

// TN tiling (G3): [k][mn], BK=64
#define ATP 272
#define A_SZT (64 * ATP)
#define ST_SZT (2 * A_SZT)
#define SMEM_TN (STAGES * ST_SZT)     // 104448

typedef __nv_bfloat16 bf16;

// ================= device scratch =================
__device__ __align__(16) bf16  g_h_hi [(size_t)8192 * 4096];
__device__ __align__(16) bf16  g_h_lo [(size_t)8192 * 4096];
__device__ __align__(16) bf16  g_x_hi [(size_t)8192 * 1024];
__device__ __align__(16) bf16  g_x_lo [(size_t)8192 * 1024];
__device__ __align__(16) bf16  g_wgu_hi[(size_t)8192 * 1024];
__device__ __align__(16) bf16  g_wgu_lo[(size_t)8192 * 1024];
__device__ __align__(16) bf16  g_proj_hi[(size_t)1024 * 1024];
__device__ __align__(16) bf16  g_proj_lo[(size_t)1024 * 1024];
__device__ __align__(16) bf16  g_t_hi [(size_t)2 * 4096 * 1024];
__device__ __align__(16) bf16  g_t_lo [(size_t)2 * 4096 * 1024];
__device__ __align__(16) bf16  g_tp_hi[(size_t)2 * 3840 * 1024];
__device__ __align__(16) bf16  g_tp_lo[(size_t)2 * 3840 * 1024];
__device__ __align__(16) float g_dd   [(size_t)2 * 15 * 1024 * 4096];
__device__ __align__(16) bf16  g_wa_hi[(size_t)2 * 16 * 1024 * 4096];
__device__ __align__(16) bf16  g_wa_lo[(size_t)2 * 16 * 1024 * 4096];
__device__ __align__(16) float g_p4   [(size_t)4 * 2 * 4096 * 1024];  // partials: [split][batch][4M]

// ================= PTX helpers =================
__device__ __forceinline__ uint32_t smem_u32(const void* p) {
    uint32_t a;
    asm("{ .reg .u64 t; cvta.to.shared.u64 t, %1; cvt.u32.u64 %0, t; }" : "=r"(a) : "l"(p));
    return a;
}
__device__ __forceinline__ void cp_async16(uint32_t sdst, const void* gsrc) {
    asm volatile("cp.async.cg.shared.global [%0], [%1], 16;" :: "r"(sdst), "l"(gsrc) : "memory");
}
__device__ __forceinline__ void cp_commit() {
    asm volatile("cp.async.commit_group;" ::: "memory");
}
__device__ __forceinline__ void ldm_x4(uint32_t addr, uint32_t& r0, uint32_t& r1,
                                       uint32_t& r2, uint32_t& r3) {
    asm volatile("ldmatrix.sync.aligned.m8n8.x4.shared.b16 {%0,%1,%2,%3}, [%4];"
                 : "=r"(r0), "=r"(r1), "=r"(r2), "=r"(r3) : "r"(addr));
}
__device__ __forceinline__ void ldm_x4_t(uint32_t addr, uint32_t& r0, uint32_t& r1,
                                         uint32_t& r2, uint32_t& r3) {
    asm volatile("ldmatrix.sync.aligned.m8n8.x4.trans.shared.b16 {%0,%1,%2,%3}, [%4];"
                 : "=r"(r0), "=r"(r1), "=r"(r2), "=r"(r3) : "r"(addr));
}
__device__ __forceinline__ void mma16816(float* c, const uint32_t* a, uint32_t b0, uint32_t b1) {
    asm volatile("mma.sync.aligned.m16n8k16.row.col.f32.bf16.bf16.f32 "
                 "{%0,%1,%2,%3}, {%4,%5,%6,%7}, {%8,%9}, {%0,%1,%2,%3};"
                 : "+f"(c[0]), "+f"(c[1]), "+f"(c[2]), "+f"(c[3])
                 : "r"(a[0]), "r"(a[1]), "r"(a[2]), "r"(a[3]), "r"(b0), "r"(b1));
}
__device__ __forceinline__ void split_bf16(float v, bf16& hi, bf16& lo) {
    hi = __float2bfloat16(v);
    lo = __float2bfloat16(v - __bfloat162float(hi));
}
__device__ __forceinline__ uint32_t pack_bf(bf16 a, bf16 b) {
    return (uint32_t)__bfloat16_as_ushort(a) | ((uint32_t)__bfloat16_as_ushort(b) << 16);
}

// ================= NT GEMM 128x128x64, bf16 hi/lo multi-pass split =================
template <int SPLIT_OUT>
__global__ __launch_bounds__(256, 2) void k_mma(
    const bf16* __restrict__ Ahi, const bf16* __restrict__ Alo, long long lda,
    const bf16* __restrict__ Bhi, const bf16* __restrict__ Blo, long long ldb,
    float* __restrict__ C, bf16* __restrict__ Chi, bf16* __restrict__ Clo,
    long long ldc, int K, int Z2, int terms,
    long long sA1, long long sA2, long long sB1, long long sB2,
    long long sC1, long long sC2)
{
    extern __shared__ char smem[];
    const uint32_t sb = smem_u32(smem);
    const int tid = threadIdx.x;
    const int lane = tid & 31;
    const int warp = tid >> 5;
    const int wm = warp >> 2;
    const int wn = warp & 3;

    const int z = blockIdx.z, z1 = z / Z2, z2 = z % Z2;
    const long long aoff = (long long)z1 * sA1 + (long long)z2 * sA2 + (long long)blockIdx.y * 128 * lda;
    const long long boff = (long long)z1 * sB1 + (long long)z2 * sB2 + (long long)blockIdx.x * 128 * ldb;
    Ahi += aoff; Alo += aoff;
    Bhi += boff; Blo += boff;
    const long long coff = (long long)z1 * sC1 + (long long)z2 * sC2
                         + (long long)blockIdx.y * 128 * ldc + (long long)blockIdx.x * 128;

    const int KI = K / BK;
    const int total = terms * KI;

    float acc[4][4][4];
#pragma unroll
    for (int i = 0; i < 4; i++)
#pragma unroll
        for (int n = 0; n < 4; n++)
#pragma unroll
            for (int r = 0; r < 4; r++) acc[i][n][r] = 0.f;

    const int lrow = tid >> 3;
    const int lko  = tid & 7;

    auto issue_load = [&](int it) {
        const int seg = (it >= 2 * KI) ? 2 : (it >= KI ? 1 : 0);
        const bf16* Ag = (seg == 2) ? Alo : Ahi;
        const bf16* Bg = (seg == 1) ? Blo : Bhi;
        const int kk = (it - seg * KI) * BK;
        const uint32_t sa = sb + (it % STAGES) * NST;
        const uint32_t sB = sa + NA_SZ;
#pragma unroll
        for (int q = 0; q < 4; q++) {
            const int row = lrow + q * 32;
            const uint32_t so = (uint32_t)row * NPITCH + lko * 16;
            cp_async16(sa + so, Ag + (size_t)row * lda + kk + lko * 8);
            cp_async16(sB + so, Bg + (size_t)row * ldb + kk + lko * 8);
        }
    };

#pragma unroll
    for (int s = 0; s < STAGES - 1; s++) {
        if (s < total) issue_load(s);
        cp_commit();
    }

    const uint32_t aRow = (uint32_t)(wm * 64 + (lane & 15));
    const uint32_t bRow = (uint32_t)(wn * 32 + (lane & 15));
    const uint32_t kByte = (uint32_t)((lane >> 4) * 16);

    for (int it = 0; it < total; ++it) {
        asm volatile("cp.async.wait_group %0;" :: "n"(STAGES - 2) : "memory");
        __syncthreads();
        const int nx = it + STAGES - 1;
        if (nx < total) issue_load(nx);
        cp_commit();

        const uint32_t sa = sb + (it % STAGES) * NST;
        const uint32_t sB = sa + NA_SZ;
#pragma unroll
        for (int k16 = 0; k16 < 4; k16++) {
            uint32_t a[4][4], b[2][4];
#pragma unroll
            for (int i = 0; i < 4; i++)
                ldm_x4(sa + (aRow + i * 16) * NPITCH + kByte + k16 * 32,
                       a[i][0], a[i][1], a[i][2], a[i][3]);
#pragma unroll
            for (int j = 0; j < 2; j++)
                ldm_x4(sB + (bRow + j * 16) * NPITCH + kByte + k16 * 32,
                       b[j][0], b[j][1], b[j][2], b[j][3]);
#pragma unroll
            for (int i = 0; i < 4; i++) {
#pragma unroll
                for (int n = 0; n < 4; n++) {
                    const int j = n >> 1, h = n & 1;
                    mma16816(acc[i][n], a[i], b[j][h], b[j][h + 2]);
                }
            }
        }
    }

    const int g = lane >> 2, t2 = (lane & 3) * 2;
#pragma unroll
    for (int i = 0; i < 4; i++) {
        const int r = wm * 64 + i * 16 + g;
#pragma unroll
        for (int n = 0; n < 4; n++) {
            const int cc = wn * 32 + (n >> 1) * 16 + (n & 1) * 8 + t2;
            if (SPLIT_OUT) {
                bf16 h0, l0, h1, l1;
                split_bf16(acc[i][n][0], h0, l0); split_bf16(acc[i][n][1], h1, l1);
                *(uint32_t*)(Chi + coff + (size_t)r * ldc + cc) = pack_bf(h0, h1);
                *(uint32_t*)(Clo + coff + (size_t)r * ldc + cc) = pack_bf(l0, l1);
                split_bf16(acc[i][n][2], h0, l0); split_bf16(acc[i][n][3], h1, l1);
                *(uint32_t*)(Chi + coff + (size_t)(r + 8) * ldc + cc) = pack_bf(h0, h1);
                *(uint32_t*)(Clo + coff + (size_t)(r + 8) * ldc + cc) = pack_bf(l0, l1);
            } else {
                *(float2*)&C[coff + (size_t)r * ldc + cc]       = make_float2(acc[i][n][0], acc[i][n][1]);
                *(float2*)&C[coff + (size_t)(r + 8) * ldc + cc] = make_float2(acc[i][n][2], acc[i][n][3]);
            }
        }
    }
}

// ================= TN GEMM 128x128x64: C[m,n] = sum_k A[k,m]*B[k,n] =================
__global__ __launch_bounds__(256, 2) void k_mma_tn(
    const bf16* __restrict__ Ahi, const bf16* __restrict__ Alo, long long lda,
    const bf16* __restrict__ Bhi, const bf16* __restrict__ Blo, long long ldb,
    float* __restrict__ C, long long ldc, int K, int Z2, int terms,
    long long sA1, long long sA2, long long sB1, long long sB2,
    long long sC1, long long sC2)
{
    extern __shared__ char smem[];
    const uint32_t sb = smem_u32(smem);
    const int tid = threadIdx.x;
    const int lane = tid & 31;
    const int warp = tid >> 5;
    const int wm = warp >> 2;
    const int wn = warp & 3;

    const int z = blockIdx.z, z1 = z / Z2, z2 = z % Z2;
    const long long aoff = (long long)z1 * sA1 + (long long)z2 * sA2 + (long long)blockIdx.y * 128;
    const long long boff = (long long)z1 * sB1 + (long long)z2 * sB2 + (long long)blockIdx.x * 128;
    Ahi += aoff; Alo += aoff;
    Bhi += boff; Blo += boff;
    C   += (long long)z1 * sC1 + (long long)z2 * sC2
         + (long long)blockIdx.y * 128 * ldc + (long long)blockIdx.x * 128;

    const int KI = K / 64;
    const int total = terms * KI;

    float acc[4][4][4];
#pragma unroll
    for (int i = 0; i < 4; i++)
#pragma unroll
        for (int n = 0; n < 4; n++)
#pragma unroll
            for (int r = 0; r < 4; r++) acc[i][n][r] = 0.f;

    auto issue_load = [&](int it) {
        const int seg = (it >= 2 * KI) ? 2 : (it >= KI ? 1 : 0);
        const bf16* Ag = (seg == 2) ? Alo : Ahi;
        const bf16* Bg = (seg == 1) ? Blo : Bhi;
        const int kk = (it - seg * KI) * 64;
        const uint32_t sa = sb + (it % STAGES) * ST_SZT;
        const uint32_t sB = sa + A_SZT;
#pragma unroll
        for (int q = 0; q < 4; q++) {
            const int c = tid + q * 256;
            const int row = c >> 4, col = c & 15;
            const uint32_t so = (uint32_t)row * ATP + col * 16;
            cp_async16(sa + so, Ag + (size_t)(kk + row) * lda + col * 8);
            cp_async16(sB + so, Bg + (size_t)(kk + row) * ldb + col * 8);
        }
    };

#pragma unroll
    for (int s = 0; s < STAGES - 1; s++) {
        if (s < total) issue_load(s);
        cp_commit();
    }

    const uint32_t aK = (lane & 7) + ((lane >> 4) & 1) * 8;
    const uint32_t aM = (uint32_t)(wm * 64) * 2 + ((lane >> 3) & 1) * 16;
    const uint32_t bK = (lane & 7) + ((lane >> 3) & 1) * 8;
    const uint32_t bN = (uint32_t)(wn * 32) * 2 + ((lane >> 4) & 1) * 16;

    for (int it = 0; it < total; ++it) {
        asm volatile("cp.async.wait_group %0;" :: "n"(STAGES - 2) : "memory");
        __syncthreads();
        const int nx = it + STAGES - 1;
        if (nx < total) issue_load(nx);
        cp_commit();

        const uint32_t sa = sb + (it % STAGES) * ST_SZT;
        const uint32_t sB = sa + A_SZT;
#pragma unroll
        for (int k16 = 0; k16 < 4; k16++) {
            uint32_t a[4][4], b[2][4];
#pragma unroll
            for (int i = 0; i < 4; i++)
                ldm_x4_t(sa + (k16 * 16 + aK) * ATP + aM + i * 32,
                         a[i][0], a[i][1], a[i][2], a[i][3]);
#pragma unroll
            for (int gidx = 0; gidx < 2; gidx++)
                ldm_x4_t(sB + (k16 * 16 + bK) * ATP + bN + gidx * 32,
                         b[gidx][0], b[gidx][1], b[gidx][2], b[gidx][3]);
#pragma unroll
            for (int i = 0; i < 4; i++) {
#pragma unroll
                for (int n = 0; n < 4; n++) {
                    const int gr = n >> 1, h = (n & 1) * 2;
                    mma16816(acc[i][n], a[i], b[gr][h], b[gr][h + 1]);
                }
            }
        }
    }

    const int g = lane >> 2, t2 = (lane & 3) * 2;
#pragma unroll
    for (int i = 0; i < 4; i++) {
        const int r = wm * 64 + i * 16 + g;
#pragma unroll
        for (int n = 0; n < 4; n++) {
            const int cc = wn * 32 + (n >> 1) * 16 + (n & 1) * 8 + t2;
            *(float2*)&C[(size_t)r * ldc + cc]       = make_float2(acc[i][n][0], acc[i][n][1]);
            *(float2*)&C[(size_t)(r + 8) * ldc + cc] = make_float2(acc[i][n][2], acc[i][n][3]);
        }
    }
}

// ================= fused G1 + SwiGLU (128 rows x 64 f-cols, BK=64, 3-term) =================
__global__ __launch_bounds__(256, 2) void k_mma_swiglu(
    const bf16* __restrict__ Ahi, const bf16* __restrict__ Alo,
    const bf16* __restrict__ Bhi, const bf16* __restrict__ Blo,
    bf16* __restrict__ Hhi, bf16* __restrict__ Hlo)
{
    extern __shared__ char smem[];
    const uint32_t sb = smem_u32(smem);
    const int tid = threadIdx.x;
    const int lane = tid & 31;
    const int warp = tid >> 5;
    const int wm = warp >> 2;
    const int wn = warp & 3;

    int l = blockIdx.y * gridDim.x + blockIdx.x;
    const int per = 8 * gridDim.x;
    const int grp = l / per, rem = l % per;
    const int by = grp * 8 + (rem & 7);
    const int bx = rem >> 3;

    const int KI = 16;
    const int total = 48;

    float accg[4][2][4], accu[4][2][4];
#pragma unroll
    for (int i = 0; i < 4; i++)
#pragma unroll
        for (int n = 0; n < 2; n++)
#pragma unroll
            for (int r = 0; r < 4; r++) { accg[i][n][r] = 0.f; accu[i][n][r] = 0.f; }

    const int lrow = tid >> 3;
    const int lko  = tid & 7;

    auto issue_load = [&](int it) {
        const int seg = (it >= 2 * KI) ? 2 : (it >= KI ? 1 : 0);
        const bf16* Ag = (seg == 2) ? Alo : Ahi;
        const bf16* Bg = (seg == 1) ? Blo : Bhi;
        const int kk = (it - seg * KI) * BK;
        const uint32_t sa = sb + (it % STAGES) * NST;
        const uint32_t sB = sa + NA_SZ;
#pragma unroll
        for (int q = 0; q < 4; q++) {
            const int row = lrow + q * 32;
            const uint32_t so = (uint32_t)row * NPITCH + lko * 16;
            cp_async16(sa + so, Ag + (size_t)(by * 128 + row) * 1024 + kk + lko * 8);
            const size_t grow = (row < 64) ? (size_t)(bx * 64 + row)
                                           : (size_t)(4096 + bx * 64 + row - 64);
            cp_async16(sB + so, Bg + grow * 1024 + kk + lko * 8);
        }
    };

#pragma unroll
    for (int s = 0; s < STAGES - 1; s++) { issue_load(s); cp_commit(); }

    const uint32_t aRow = (uint32_t)(wm * 64 + (lane & 15));
    const uint32_t gRow = (uint32_t)(wn * 16 + (lane & 15));
    const uint32_t uRow = gRow + 64;
    const uint32_t kByte = (uint32_t)((lane >> 4) * 16);

    for (int it = 0; it < total; ++it) {
        asm volatile("cp.async.wait_group %0;" :: "n"(STAGES - 2) : "memory");
        __syncthreads();
        const int nx = it + STAGES - 1;
        if (nx < total) issue_load(nx);
        cp_commit();

        const uint32_t sa = sb + (it % STAGES) * NST;
        const uint32_t sB = sa + NA_SZ;
#pragma unroll
        for (int k16 = 0; k16 < 4; k16++) {
            uint32_t a[4][4], bg[4], bu[4];
#pragma unroll
            for (int i = 0; i < 4; i++)
                ldm_x4(sa + (aRow + i * 16) * NPITCH + kByte + k16 * 32,
                       a[i][0], a[i][1], a[i][2], a[i][3]);
            ldm_x4(sB + gRow * NPITCH + kByte + k16 * 32, bg[0], bg[1], bg[2], bg[3]);
            ldm_x4(sB + uRow * NPITCH + kByte + k16 * 32, bu[0], bu[1], bu[2], bu[3]);
#pragma unroll
            for (int i = 0; i < 4; i++) {
#pragma unroll
                for (int n = 0; n < 2; n++) {
                    mma16816(accg[i][n], a[i], bg[n], bg[n + 2]);
                    mma16816(accu[i][n], a[i], bu[n], bu[n + 2]);
                }
            }
        }
    }

    const int g = lane >> 2, t2 = (lane & 3) * 2;
#pragma unroll
    for (int i = 0; i < 4; i++) {
#pragma unroll
        for (int n = 0; n < 2; n++) {
            const int col = bx * 64 + wn * 16 + n * 8 + t2;
#pragma unroll
            for (int half = 0; half < 2; half++) {
                const size_t row = (size_t)by * 128 + wm * 64 + i * 16 + g + half * 8;
                float g0 = accg[i][n][half * 2 + 0], g1 = accg[i][n][half * 2 + 1];
                float u0 = accu[i][n][half * 2 + 0], u1 = accu[i][n][half * 2 + 1];
                float h0 = g0 / (1.0f + expf(-g0)) * u0;
                float h1 = g1 / (1.0f + expf(-g1)) * u1;
                bf16 h0h, h0l, h1h, h1l;
                split_bf16(h0, h0h, h0l); split_bf16(h1, h1h, h1l);
                *(uint32_t*)(Hhi + row * 4096 + col) = pack_bf(h0h, h1h);
                *(uint32_t*)(Hlo + row * 4096 + col) = pack_bf(h0l, h1l);
            }
        }
    }
}

// ================= elementwise kernels =================
__global__ void k_convert4(const float* __restrict__ in, bf16* __restrict__ hi,
                           bf16* __restrict__ lo, long long n)
{
    long long i = ((long long)blockIdx.x * blockDim.x + threadIdx.x) * 4;
    if (i >= n) return;
    float4 v = *(const float4*)(in + i);
    bf16 h[4], l[4];
    split_bf16(v.x, h[0], l[0]); split_bf16(v.y, h[1], l[1]);
    split_bf16(v.z, h[2], l[2]); split_bf16(v.w, h[3], l[3]);
    *(uint2*)(hi + i) = make_uint2(pack_bf(h[0], h[1]), pack_bf(h[2], h[3]));
    *(uint2*)(lo + i) = make_uint2(pack_bf(l[0], l[1]), pack_bf(l[2], l[3]));
}

__global__ void k_conv_split4(const float* __restrict__ tt, const float* __restrict__ cw,
                              const float* __restrict__ cb, bf16* __restrict__ thi,
                              bf16* __restrict__ tlo)
{
    long long idx = (long long)blockIdx.x * blockDim.x + threadIdx.x;
    if (idx >= (long long)2 * 4096 * 256) return;
    int d4 = (int)(idx & 255) * 4;
    long long bi = idx >> 8;
    int i = (int)(bi & 4095);
    int b = (int)(bi >> 12);
    const float* base = tt + (long long)b * 4096 * 1024 + d4;
    float4 acc = *(const float4*)(cb + d4);
#pragma unroll
    for (int k = 0; k < KSIZE; k++) {
        int src = i - (KSIZE - 1) + k;
        if (src >= 0) {
            float4 v = *(const float4*)(base + (long long)src * 1024);
            acc.x += v.x * cw[(d4 + 0) * KSIZE + k];
            acc.y += v.y * cw[(d4 + 1) * KSIZE + k];
            acc.z += v.z * cw[(d4 + 2) * KSIZE + k];
            acc.w += v.w * cw[(d4 + 3) * KSIZE + k];
        }
    }
    bf16 h[4], l[4];
    split_bf16(acc.x, h[0], l[0]); split_bf16(acc.y, h[1], l[1]);
    split_bf16(acc.z, h[2], l[2]); split_bf16(acc.w, h[3], l[3]);
    size_t o = ((size_t)b * 4096 + i) * 1024 + d4;
    *(uint2*)(thi + o) = make_uint2(pack_bf(h[0], h[1]), pack_bf(h[2], h[3]));
    *(uint2*)(tlo + o) = make_uint2(pack_bf(l[0], l[1]), pack_bf(l[2], l[3]));
}

// per-batch cumsum of dd -> wa hi/lo (vectorized x4); pointers pre-offset by batch
__global__ void k_wadp4b(const float* __restrict__ dd, const float* __restrict__ wdown,
                         bf16* __restrict__ whi, bf16* __restrict__ wlo)
{
    long long i = ((long long)blockIdx.x * blockDim.x + threadIdx.x) * 4;
    const long long DF = 1LL << 22;
    if (i >= DF) return;
    float4 acc = *(const float4*)(wdown + i);
#pragma unroll
    for (int j = 0; j < 16; j++) {
        bf16 h[4], l[4];
        split_bf16(acc.x, h[0], l[0]); split_bf16(acc.y, h[1], l[1]);
        split_bf16(acc.z, h[2], l[2]); split_bf16(acc.w, h[3], l[3]);
        size_t o = ((size_t)j << 22) + i;
        *(uint2*)(whi + o) = make_uint2(pack_bf(h[0], h[1]), pack_bf(h[2], h[3]));
        *(uint2*)(wlo + o) = make_uint2(pack_bf(l[0], l[1]), pack_bf(l[2], l[3]));
        if (j < 15) {
            float4 d4 = *(const float4*)(dd + ((size_t)j << 22) + i);
            acc.x += TTT_LR * d4.x; acc.y += TTT_LR * d4.y;
            acc.z += TTT_LR * d4.z; acc.w += TTT_LR * d4.w;
        }
    }
}

// per-batch reduce of 2 split-K partials; pointers pre-offset by batch
__global__ void k_reduce2b(const float* __restrict__ p0, const float* __restrict__ p1,
                           float* __restrict__ out)
{
    const long long N = 1LL << 22;   // one batch
    long long i = ((long long)blockIdx.x * blockDim.x + threadIdx.x) * 4;
    if (i >= N) return;
    float4 a = *(const float4*)(p0 + i);
    float4 b = *(const float4*)(p1 + i);
    *(float4*)(out + i) = make_float4(a.x + b.x, a.y + b.y, a.z + b.z, a.w + b.w);
}

// ================= launch =================
extern "C" void kernel_launch(void* const* d_in, const int* in_sizes, int n_in,
                              void* d_out, int out_size)
{
    const float* x     = (const float*)d_in[0];
    const float* tt    = (const float*)d_in[1];
    const float* wgu   = (const float*)d_in[2];
    const float* wdown = (const float*)d_in[3];
    const float* proj  = (const float*)d_in[4];
    const float* cw    = (const float*)d_in[5];
    const float* cb    = (const float*)d_in[6];
    float* out = (float*)d_out;

    bf16 *h_hi, *h_lo, *x_hi, *x_lo, *wgu_hi, *wgu_lo, *proj_hi, *proj_lo;
    bf16 *t_hi, *t_lo, *tp_hi, *tp_lo, *wa_hi, *wa_lo;
    float *dd, *p4;
    cudaGetSymbolAddress((void**)&h_hi, g_h_hi);     cudaGetSymbolAddress((void**)&h_lo, g_h_lo);
    cudaGetSymbolAddress((void**)&x_hi, g_x_hi);     cudaGetSymbolAddress((void**)&x_lo, g_x_lo);
    cudaGetSymbolAddress((void**)&wgu_hi, g_wgu_hi); cudaGetSymbolAddress((void**)&wgu_lo, g_wgu_lo);
    cudaGetSymbolAddress((void**)&proj_hi, g_proj_hi); cudaGetSymbolAddress((void**)&proj_lo, g_proj_lo);
    cudaGetSymbolAddress((void**)&t_hi, g_t_hi);     cudaGetSymbolAddress((void**)&t_lo, g_t_lo);
    cudaGetSymbolAddress((void**)&tp_hi, g_tp_hi);   cudaGetSymbolAddress((void**)&tp_lo, g_tp_lo);
    cudaGetSymbolAddress((void**)&wa_hi, g_wa_hi);   cudaGetSymbolAddress((void**)&wa_lo, g_wa_lo);
    cudaGetSymbolAddress((void**)&dd, g_dd);
    cudaGetSymbolAddress((void**)&p4, g_p4);

    static bool s_init = false;
    static cudaStream_t s1, s2;
    static cudaEvent_t evFork, evWgu, evSide, evD0, evD1, evW0, evW1, evG40, evR0;
    if (!s_init) {
        s_init = true;
        cudaStreamCreateWithFlags(&s1, cudaStreamNonBlocking);
        cudaStreamCreateWithFlags(&s2, cudaStreamNonBlocking);
        cudaEventCreateWithFlags(&evFork, cudaEventDisableTiming);
        cudaEventCreateWithFlags(&evWgu,  cudaEventDisableTiming);
        cudaEventCreateWithFlags(&evSide, cudaEventDisableTiming);
        cudaEventCreateWithFlags(&evD0,   cudaEventDisableTiming);
        cudaEventCreateWithFlags(&evD1,   cudaEventDisableTiming);
        cudaEventCreateWithFlags(&evW0,   cudaEventDisableTiming);
        cudaEventCreateWithFlags(&evW1,   cudaEventDisableTiming);
        cudaEventCreateWithFlags(&evG40,  cudaEventDisableTiming);
        cudaEventCreateWithFlags(&evR0,   cudaEventDisableTiming);
        cudaFuncSetAttribute(k_mma<0>, cudaFuncAttributeMaxDynamicSharedMemorySize, SMEM_NT);
        cudaFuncSetAttribute(k_mma<1>, cudaFuncAttributeMaxDynamicSharedMemorySize, SMEM_NT);
        cudaFuncSetAttribute(k_mma_tn, cudaFuncAttributeMaxDynamicSharedMemorySize, SMEM_TN);
        cudaFuncSetAttribute(k_mma_swiglu, cudaFuncAttributeMaxDynamicSharedMemorySize, SMEM_NT);
    }

    const long long DF   = 1LL << 22;             // 1024*4096
    const long long HB   = 4096LL * 4096;         // h batch stride
    const long long WAB  = 16LL * DF;             // wa batch stride
    const long long DDB  = 15LL * DF;             // dd batch stride
    const long long TPB  = 3840LL * 1024;         // tp batch stride
    const long long PB   = DF;                    // p4 batch stride
    const long long PS   = 2LL * DF;              // p4 split stride

    // fork
    cudaEventRecord(evFork, 0);
    cudaStreamWaitEvent(s1, evFork, 0);
    cudaStreamWaitEvent(s2, evFork, 0);

    // s2: wgu convert (feeds G1)
    k_convert4<<<(int)((8192LL * 1024 / 4 + 255) / 256), 256, 0, s2>>>(
        wgu, wgu_hi, wgu_lo, 8192LL * 1024);
    cudaEventRecord(evWgu, s2);

    // s1: conv -> proj convert -> G2 (1-term split)
    k_conv_split4<<<(int)((2LL * 4096 * 256 + 255) / 256), 256, 0, s1>>>(tt, cw, cb, t_hi, t_lo);
    k_convert4<<<(int)((1024LL * 1024 / 4 + 255) / 256), 256, 0, s1>>>(
        proj, proj_hi, proj_lo, 1024LL * 1024);
    k_mma<1><<<dim3(8, 30, 2), 256, SMEM_NT, s1>>>(
        t_hi, t_lo, 1024, proj_hi, proj_lo, 1024,
        nullptr, tp_hi, tp_lo, 1024, 1024, 1, /*terms=*/1,
        4096LL * 1024, 0, 0, 0, TPB, 0);
    cudaEventRecord(evSide, s1);

    // null: x convert -> (join wgu) -> G1 (3-term)
    k_convert4<<<(int)((8192LL * 1024 / 4 + 255) / 256), 256>>>(x, x_hi, x_lo, 8192LL * 1024);
    cudaStreamWaitEvent(0, evWgu, 0);
    k_mma_swiglu<<<dim3(64, 64, 1), 256, SMEM_NT>>>(x_hi, x_lo, wgu_hi, wgu_lo, h_hi, h_lo);

    // join side chain before G3
    cudaStreamWaitEvent(0, evSide, 0);

    // G3 batch 0 (TN, 1-term)
    k_mma_tn<<<dim3(32, 8, 15), 256, SMEM_TN>>>(
        tp_hi, tp_lo, 1024, h_hi, h_lo, 4096, dd, 4096, 256, 15, /*terms=*/1,
        0, 256LL * 1024, 0, 256LL * 4096, 0, DF);
    cudaEventRecord(evD0, 0);

    // G3 batch 1 on null, wadp(b0) on s1 concurrently
    cudaStreamWaitEvent(s1, evD0, 0);
    k_wadp4b<<<(int)((DF / 4 + 255) / 256), 256, 0, s1>>>(dd, wdown, wa_hi, wa_lo);
    cudaEventRecord(evW0, s1);

    k_mma_tn<<<dim3(32, 8, 15), 256, SMEM_TN>>>(
        tp_hi + TPB, tp_lo + TPB, 1024, h_hi + HB, h_lo + HB, 4096,
        dd + DDB, 4096, 256, 15, /*terms=*/1,
        0, 256LL * 1024, 0, 256LL * 4096, 0, DF);
    cudaEventRecord(evD1, 0);

    // wadp(b1) on s1 after G3(b1), concurrent with G4(b0)
    cudaStreamWaitEvent(s1, evD1, 0);
    k_wadp4b<<<(int)((DF / 4 + 255) / 256), 256, 0, s1>>>(
        dd + DDB, wdown, wa_hi + WAB, wa_lo + WAB);
    cudaEventRecord(evW1, s1);

    // G4 batch 0 (split-K=2, 3-term) after wadp(b0)
    cudaStreamWaitEvent(0, evW0, 0);
    k_mma<0><<<dim3(8, 2, 32), 256, SMEM_NT>>>(
        h_hi, h_lo, 4096, wa_hi, wa_lo, 4096,
        p4, nullptr, nullptr, 1024, 2048, 2, /*terms=*/3,
        256LL * 4096, 2048, DF, 2048,
        256LL * 1024, PS);
    cudaEventRecord(evG40, 0);

    // reduce(b0) on s2 concurrent with G4(b1)
    cudaStreamWaitEvent(s2, evG40, 0);
    k_reduce2b<<<(int)((DF / 4 + 255) / 256), 256, 0, s2>>>(p4, p4 + PS, out);
    cudaEventRecord(evR0, s2);

    // G4 batch 1 after wadp(b1)
    cudaStreamWaitEvent(0, evW1, 0);
    k_mma<0><<<dim3(8, 2, 32), 256, SMEM_NT>>>(
        h_hi + HB, h_lo + HB, 4096, wa_hi + WAB, wa_lo + WAB, 4096,
        p4 + PB, nullptr, nullptr, 1024, 2048, 2, /*terms=*/3,
        256LL * 4096, 2048, DF, 2048,
        256LL * 1024, PS);

    // reduce(b1) on null, then join reduce(b0)
    k_reduce2b<<<(int)((DF / 4 + 255) / 256), 256>>>(p4 + PB, p4 + PS + PB, out + DF);
    cudaStreamWaitEvent(0, evR0, 0);
}

// round 15
// speedup vs baseline: 1.0324x; 1.0324x over previous
#include <cuda_runtime.h>
#include <cuda_bf16.h>
#include <cstdint>

#define TTT_LR  0.01f
#define KSIZE   5

// NT tiling: 128x128x64, 8 warps of 64x32, occ 2
#define BK 64
#define NPITCH 144
#define NA_SZ (128 * NPITCH)
#define NST (2 * NA_SZ)
#define STAGES 3
#define SMEM_NT (STAGES * NST)        // 110592

// TN tiling (G3): [k][mn], BK=64
#define ATP 272
#define A_SZT (64 * ATP)
#define ST_SZT (2 * A_SZT)
#define SMEM_TN (STAGES * ST_SZT)     // 104448

typedef __nv_bfloat16 bf16;

// ================= device scratch =================
__device__ __align__(16) bf16  g_h_hi [(size_t)8192 * 4096];
__device__ __align__(16) bf16  g_h_lo [(size_t)8192 * 4096];
__device__ __align__(16) bf16  g_x_hi [(size_t)8192 * 1024];
__device__ __align__(16) bf16  g_x_lo [(size_t)8192 * 1024];
__device__ __align__(16) bf16  g_wgu_hi[(size_t)8192 * 1024];
__device__ __align__(16) bf16  g_wgu_lo[(size_t)8192 * 1024];
__device__ __align__(16) bf16  g_proj_hi[(size_t)1024 * 1024];
__device__ __align__(16) bf16  g_proj_lo[(size_t)1024 * 1024];
__device__ __align__(16) bf16  g_t_hi [(size_t)2 * 4096 * 1024];
__device__ __align__(16) bf16  g_t_lo [(size_t)2 * 4096 * 1024];
__device__ __align__(16) bf16  g_tp_hi[(size_t)2 * 3840 * 1024];
__device__ __align__(16) bf16  g_tp_lo[(size_t)2 * 3840 * 1024];
__device__ __align__(16) float g_dd   [(size_t)2 * 15 * 1024 * 4096];
__device__ __align__(16) bf16  g_wa_hi[(size_t)2 * 16 * 1024 * 4096];
__device__ __align__(16) bf16  g_wa_lo[(size_t)2 * 16 * 1024 * 4096];
__device__ __align__(16) float g_p4   [(size_t)4 * 2 * 4096 * 1024];  // partials: [split][batch][4M]

// ================= PTX helpers =================
__device__ __forceinline__ uint32_t smem_u32(const void* p) {
    uint32_t a;
    asm("{ .reg .u64 t; cvta.to.shared.u64 t, %1; cvt.u32.u64 %0, t; }" : "=r"(a) : "l"(p));
    return a;
}
__device__ __forceinline__ void cp_async16(uint32_t sdst, const void* gsrc) {
    asm volatile("cp.async.cg.shared.global [%0], [%1], 16;" :: "r"(sdst), "l"(gsrc) : "memory");
}
__device__ __forceinline__ void cp_commit() {
    asm volatile("cp.async.commit_group;" ::: "memory");
}
__device__ __forceinline__ void ldm_x4(uint32_t addr, uint32_t& r0, uint32_t& r1,
                                       uint32_t& r2, uint32_t& r3) {
    asm volatile("ldmatrix.sync.aligned.m8n8.x4.shared.b16 {%0,%1,%2,%3}, [%4];"
                 : "=r"(r0), "=r"(r1), "=r"(r2), "=r"(r3) : "r"(addr));
}
__device__ __forceinline__ void ldm_x4_t(uint32_t addr, uint32_t& r0, uint32_t& r1,
                                         uint32_t& r2, uint32_t& r3) {
    asm volatile("ldmatrix.sync.aligned.m8n8.x4.trans.shared.b16 {%0,%1,%2,%3}, [%4];"
                 : "=r"(r0), "=r"(r1), "=r"(r2), "=r"(r3) : "r"(addr));
}
__device__ __forceinline__ void mma16816(float* c, const uint32_t* a, uint32_t b0, uint32_t b1) {
    asm volatile("mma.sync.aligned.m16n8k16.row.col.f32.bf16.bf16.f32 "
                 "{%0,%1,%2,%3}, {%4,%5,%6,%7}, {%8,%9}, {%0,%1,%2,%3};"
                 : "+f"(c[0]), "+f"(c[1]), "+f"(c[2]), "+f"(c[3])
                 : "r"(a[0]), "r"(a[1]), "r"(a[2]), "r"(a[3]), "r"(b0), "r"(b1));
}
__device__ __forceinline__ void split_bf16(float v, bf16& hi, bf16& lo) {
    hi = __float2bfloat16(v);
    lo = __float2bfloat16(v - __bfloat162float(hi));
}
__device__ __forceinline__ uint32_t pack_bf(bf16 a, bf16 b) {
    return (uint32_t)__bfloat16_as_ushort(a) | ((uint32_t)__bfloat16_as_ushort(b) << 16);
}

// ================= NT GEMM 128x128x64, bf16 hi/lo multi-pass split =================
template <int SPLIT_OUT>
__global__ __launch_bounds__(256, 2) void k_mma(
    const bf16* __restrict__ Ahi, const bf16* __restrict__ Alo, long long lda,
    const bf16* __restrict__ Bhi, const bf16* __restrict__ Blo, long long ldb,
    float* __restrict__ C, bf16* __restrict__ Chi, bf16* __restrict__ Clo,
    long long ldc, int K, int Z2, int terms,
    long long sA1, long long sA2, long long sB1, long long sB2,
    long long sC1, long long sC2)
{
    extern __shared__ char smem[];
    const uint32_t sb = smem_u32(smem);
    const int tid = threadIdx.x;
    const int lane = tid & 31;
    const int warp = tid >> 5;
    const int wm = warp >> 2;
    const int wn = warp & 3;

    const int z = blockIdx.z, z1 = z / Z2, z2 = z % Z2;
    const long long aoff = (long long)z1 * sA1 + (long long)z2 * sA2 + (long long)blockIdx.y * 128 * lda;
    const long long boff = (long long)z1 * sB1 + (long long)z2 * sB2 + (long long)blockIdx.x * 128 * ldb;
    Ahi += aoff; Alo += aoff;
    Bhi += boff; Blo += boff;
    const long long coff = (long long)z1 * sC1 + (long long)z2 * sC2
                         + (long long)blockIdx.y * 128 * ldc + (long long)blockIdx.x * 128;

    const int KI = K / BK;
    const int total = terms * KI;

    float acc[4][4][4];
#pragma unroll
    for (int i = 0; i < 4; i++)
#pragma unroll
        for (int n = 0; n < 4; n++)
#pragma unroll
            for (int r = 0; r < 4; r++) acc[i][n][r] = 0.f;

    const int lrow = tid >> 3;
    const int lko  = tid & 7;

    auto issue_load = [&](int it) {
        const int seg = (it >= 2 * KI) ? 2 : (it >= KI ? 1 : 0);
        const bf16* Ag = (seg == 2) ? Alo : Ahi;
        const bf16* Bg = (seg == 1) ? Blo : Bhi;
        const int kk = (it - seg * KI) * BK;
        const uint32_t sa = sb + (it % STAGES) * NST;
        const uint32_t sB = sa + NA_SZ;
#pragma unroll
        for (int q = 0; q < 4; q++) {
            const int row = lrow + q * 32;
            const uint32_t so = (uint32_t)row * NPITCH + lko * 16;
            cp_async16(sa + so, Ag + (size_t)row * lda + kk + lko * 8);
            cp_async16(sB + so, Bg + (size_t)row * ldb + kk + lko * 8);
        }
    };

#pragma unroll
    for (int s = 0; s < STAGES - 1; s++) {
        if (s < total) issue_load(s);
        cp_commit();
    }

    const uint32_t aRow = (uint32_t)(wm * 64 + (lane & 15));
    const uint32_t bRow = (uint32_t)(wn * 32 + (lane & 15));
    const uint32_t kByte = (uint32_t)((lane >> 4) * 16);

    for (int it = 0; it < total; ++it) {
        asm volatile("cp.async.wait_group %0;" :: "n"(STAGES - 2) : "memory");
        __syncthreads();
        const int nx = it + STAGES - 1;
        if (nx < total) issue_load(nx);
        cp_commit();

        const uint32_t sa = sb + (it % STAGES) * NST;
        const uint32_t sB = sa + NA_SZ;
#pragma unroll
        for (int k16 = 0; k16 < 4; k16++) {
            uint32_t a[4][4], b[2][4];
#pragma unroll
            for (int i = 0; i < 4; i++)
                ldm_x4(sa + (aRow + i * 16) * NPITCH + kByte + k16 * 32,
                       a[i][0], a[i][1], a[i][2], a[i][3]);
#pragma unroll
            for (int j = 0; j < 2; j++)
                ldm_x4(sB + (bRow + j * 16) * NPITCH + kByte + k16 * 32,
                       b[j][0], b[j][1], b[j][2], b[j][3]);
#pragma unroll
            for (int i = 0; i < 4; i++) {
#pragma unroll
                for (int n = 0; n < 4; n++) {
                    const int j = n >> 1, h = n & 1;
                    mma16816(acc[i][n], a[i], b[j][h], b[j][h + 2]);
                }
            }
        }
    }

    const int g = lane >> 2, t2 = (lane & 3) * 2;
#pragma unroll
    for (int i = 0; i < 4; i++) {
        const int r = wm * 64 + i * 16 + g;
#pragma unroll
        for (int n = 0; n < 4; n++) {
            const int cc = wn * 32 + (n >> 1) * 16 + (n & 1) * 8 + t2;
            if (SPLIT_OUT) {
                bf16 h0, l0, h1, l1;
                split_bf16(acc[i][n][0], h0, l0); split_bf16(acc[i][n][1], h1, l1);
                *(uint32_t*)(Chi + coff + (size_t)r * ldc + cc) = pack_bf(h0, h1);
                *(uint32_t*)(Clo + coff + (size_t)r * ldc + cc) = pack_bf(l0, l1);
                split_bf16(acc[i][n][2], h0, l0); split_bf16(acc[i][n][3], h1, l1);
                *(uint32_t*)(Chi + coff + (size_t)(r + 8) * ldc + cc) = pack_bf(h0, h1);
                *(uint32_t*)(Clo + coff + (size_t)(r + 8) * ldc + cc) = pack_bf(l0, l1);
            } else {
                *(float2*)&C[coff + (size_t)r * ldc + cc]       = make_float2(acc[i][n][0], acc[i][n][1]);
                *(float2*)&C[coff + (size_t)(r + 8) * ldc + cc] = make_float2(acc[i][n][2], acc[i][n][3]);
            }
        }
    }
}

// ================= TN GEMM 128x128x64: C[m,n] = sum_k A[k,m]*B[k,n] =================
__global__ __launch_bounds__(256, 2) void k_mma_tn(
    const bf16* __restrict__ Ahi, const bf16* __restrict__ Alo, long long lda,
    const bf16* __restrict__ Bhi, const bf16* __restrict__ Blo, long long ldb,
    float* __restrict__ C, long long ldc, int K, int Z2, int terms,
    long long sA1, long long sA2, long long sB1, long long sB2,
    long long sC1, long long sC2)
{
    extern __shared__ char smem[];
    const uint32_t sb = smem_u32(smem);
    const int tid = threadIdx.x;
    const int lane = tid & 31;
    const int warp = tid >> 5;
    const int wm = warp >> 2;
    const int wn = warp & 3;

    const int z = blockIdx.z, z1 = z / Z2, z2 = z % Z2;
    const long long aoff = (long long)z1 * sA1 + (long long)z2 * sA2 + (long long)blockIdx.y * 128;
    const long long boff = (long long)z1 * sB1 + (long long)z2 * sB2 + (long long)blockIdx.x * 128;
    Ahi += aoff; Alo += aoff;
    Bhi += boff; Blo += boff;
    C   += (long long)z1 * sC1 + (long long)z2 * sC2
         + (long long)blockIdx.y * 128 * ldc + (long long)blockIdx.x * 128;

    const int KI = K / 64;
    const int total = terms * KI;

    float acc[4][4][4];
#pragma unroll
    for (int i = 0; i < 4; i++)
#pragma unroll
        for (int n = 0; n < 4; n++)
#pragma unroll
            for (int r = 0; r < 4; r++) acc[i][n][r] = 0.f;

    auto issue_load = [&](int it) {
        const int seg = (it >= 2 * KI) ? 2 : (it >= KI ? 1 : 0);
        const bf16* Ag = (seg == 2) ? Alo : Ahi;
        const bf16* Bg = (seg == 1) ? Blo : Bhi;
        const int kk = (it - seg * KI) * 64;
        const uint32_t sa = sb + (it % STAGES) * ST_SZT;
        const uint32_t sB = sa + A_SZT;
#pragma unroll
        for (int q = 0; q < 4; q++) {
            const int c = tid + q * 256;
            const int row = c >> 4, col = c & 15;
            const uint32_t so = (uint32_t)row * ATP + col * 16;
            cp_async16(sa + so, Ag + (size_t)(kk + row) * lda + col * 8);
            cp_async16(sB + so, Bg + (size_t)(kk + row) * ldb + col * 8);
        }
    };

#pragma unroll
    for (int s = 0; s < STAGES - 1; s++) {
        if (s < total) issue_load(s);
        cp_commit();
    }

    const uint32_t aK = (lane & 7) + ((lane >> 4) & 1) * 8;
    const uint32_t aM = (uint32_t)(wm * 64) * 2 + ((lane >> 3) & 1) * 16;
    const uint32_t bK = (lane & 7) + ((lane >> 3) & 1) * 8;
    const uint32_t bN = (uint32_t)(wn * 32) * 2 + ((lane >> 4) & 1) * 16;

    for (int it = 0; it < total; ++it) {
        asm volatile("cp.async.wait_group %0;" :: "n"(STAGES - 2) : "memory");
        __syncthreads();
        const int nx = it + STAGES - 1;
        if (nx < total) issue_load(nx);
        cp_commit();

        const uint32_t sa = sb + (it % STAGES) * ST_SZT;
        const uint32_t sB = sa + A_SZT;
#pragma unroll
        for (int k16 = 0; k16 < 4; k16++) {
            uint32_t a[4][4], b[2][4];
#pragma unroll
            for (int i = 0; i < 4; i++)
                ldm_x4_t(sa + (k16 * 16 + aK) * ATP + aM + i * 32,
                         a[i][0], a[i][1], a[i][2], a[i][3]);
#pragma unroll
            for (int gidx = 0; gidx < 2; gidx++)
                ldm_x4_t(sB + (k16 * 16 + bK) * ATP + bN + gidx * 32,
                         b[gidx][0], b[gidx][1], b[gidx][2], b[gidx][3]);
#pragma unroll
            for (int i = 0; i < 4; i++) {
#pragma unroll
                for (int n = 0; n < 4; n++) {
                    const int gr = n >> 1, h = (n & 1) * 2;
                    mma16816(acc[i][n], a[i], b[gr][h], b[gr][h + 1]);
                }
            }
        }
    }

    const int g = lane >> 2, t2 = (lane & 3) * 2;
#pragma unroll
    for (int i = 0; i < 4; i++) {
        const int r = wm * 64 + i * 16 + g;
#pragma unroll
        for (int n = 0; n < 4; n++) {
            const int cc = wn * 32 + (n >> 1) * 16 + (n & 1) * 8 + t2;
            *(float2*)&C[(size_t)r * ldc + cc]       = make_float2(acc[i][n][0], acc[i][n][1]);
            *(float2*)&C[(size_t)(r + 8) * ldc + cc] = make_float2(acc[i][n][2], acc[i][n][3]);
        }
    }
}

// ================= fused G1 + SwiGLU (128 rows x 64 f-cols, BK=64, 3-term) =================
__global__ __launch_bounds__(256, 2) void k_mma_swiglu(
    const bf16* __restrict__ Ahi, const bf16* __restrict__ Alo,
    const bf16* __restrict__ Bhi, const bf16* __restrict__ Blo,
    bf16* __restrict__ Hhi, bf16* __restrict__ Hlo)
{
    extern __shared__ char smem[];
    const uint32_t sb = smem_u32(smem);
    const int tid = threadIdx.x;
    const int lane = tid & 31;
    const int warp = tid >> 5;
    const int wm = warp >> 2;
    const int wn = warp & 3;

    int l = blockIdx.y * gridDim.x + blockIdx.x;
    const int per = 8 * gridDim.x;
    const int grp = l / per, rem = l % per;
    const int by = grp * 8 + (rem & 7);
    const int bx = rem >> 3;

    const int KI = 16;
    const int total = 48;

    float accg[4][2][4], accu[4][2][4];
#pragma unroll
    for (int i = 0; i < 4; i++)
#pragma unroll
        for (int n = 0; n < 2; n++)
#pragma unroll
            for (int r = 0; r < 4; r++) { accg[i][n][r] = 0.f; accu[i][n][r] = 0.f; }

    const int lrow = tid >> 3;
    const int lko  = tid & 7;

    auto issue_load = [&](int it) {
        const int seg = (it >= 2 * KI) ? 2 : (it >= KI ? 1 : 0);
        const bf16* Ag = (seg == 2) ? Alo : Ahi;
        const bf16* Bg = (seg == 1) ? Blo : Bhi;
        const int kk = (it - seg * KI) * BK;
        const uint32_t sa = sb + (it % STAGES) * NST;
        const uint32_t sB = sa + NA_SZ;
#pragma unroll
        for (int q = 0; q < 4; q++) {
            const int row = lrow + q * 32;
            const uint32_t so = (uint32_t)row * NPITCH + lko * 16;
            cp_async16(sa + so, Ag + (size_t)(by * 128 + row) * 1024 + kk + lko * 8);
            const size_t grow = (row < 64) ? (size_t)(bx * 64 + row)
                                           : (size_t)(4096 + bx * 64 + row - 64);
            cp_async16(sB + so, Bg + grow * 1024 + kk + lko * 8);
        }
    };

#pragma unroll
    for (int s = 0; s < STAGES - 1; s++) { issue_load(s); cp_commit(); }

    const uint32_t aRow = (uint32_t)(wm * 64 + (lane & 15));
    const uint32_t gRow = (uint32_t)(wn * 16 + (lane & 15));
    const uint32_t uRow = gRow + 64;
    const uint32_t kByte = (uint32_t)((lane >> 4) * 16);

    for (int it = 0; it < total; ++it) {
        asm volatile("cp.async.wait_group %0;" :: "n"(STAGES - 2) : "memory");
        __syncthreads();
        const int nx = it + STAGES - 1;
        if (nx < total) issue_load(nx);
        cp_commit();

        const uint32_t sa = sb + (it % STAGES) * NST;
        const uint32_t sB = sa + NA_SZ;
#pragma unroll
        for (int k16 = 0; k16 < 4; k16++) {
            uint32_t a[4][4], bg[4], bu[4];
#pragma unroll
            for (int i = 0; i < 4; i++)
                ldm_x4(sa + (aRow + i * 16) * NPITCH + kByte + k16 * 32,
                       a[i][0], a[i][1], a[i][2], a[i][3]);
            ldm_x4(sB + gRow * NPITCH + kByte + k16 * 32, bg[0], bg[1], bg[2], bg[3]);
            ldm_x4(sB + uRow * NPITCH + kByte + k16 * 32, bu[0], bu[1], bu[2], bu[3]);
#pragma unroll
            for (int i = 0; i < 4; i++) {
#pragma unroll
                for (int n = 0; n < 2; n++) {
                    mma16816(accg[i][n], a[i], bg[n], bg[n + 2]);
                    mma16816(accu[i][n], a[i], bu[n], bu[n + 2]);
                }
            }
        }
    }

    const int g = lane >> 2, t2 = (lane & 3) * 2;
#pragma unroll
    for (int i = 0; i < 4; i++) {
#pragma unroll
        for (int n = 0; n < 2; n++) {
            const int col = bx * 64 + wn * 16 + n * 8 + t2;
#pragma unroll
            for (int half = 0; half < 2; half++) {
                const size_t row = (size_t)by * 128 + wm * 64 + i * 16 + g + half * 8;
                float g0 = accg[i][n][half * 2 + 0], g1 = accg[i][n][half * 2 + 1];
                float u0 = accu[i][n][half * 2 + 0], u1 = accu[i][n][half * 2 + 1];
                float h0 = g0 / (1.0f + expf(-g0)) * u0;
                float h1 = g1 / (1.0f + expf(-g1)) * u1;
                bf16 h0h, h0l, h1h, h1l;
                split_bf16(h0, h0h, h0l); split_bf16(h1, h1h, h1l);
                *(uint32_t*)(Hhi + row * 4096 + col) = pack_bf(h0h, h1h);
                *(uint32_t*)(Hlo + row * 4096 + col) = pack_bf(h0l, h1l);
            }
        }
    }
}

// ================= elementwise kernels =================
__global__ void k_convert4(const float* __restrict__ in, bf16* __restrict__ hi,
                           bf16* __restrict__ lo, long long n)
{
    long long i = ((long long)blockIdx.x * blockDim.x + threadIdx.x) * 4;
    if (i >= n) return;
    float4 v = *(const float4*)(in + i);
    bf16 h[4], l[4];
    split_bf16(v.x, h[0], l[0]); split_bf16(v.y, h[1], l[1]);
    split_bf16(v.z, h[2], l[2]); split_bf16(v.w, h[3], l[3]);
    *(uint2*)(hi + i) = make_uint2(pack_bf(h[0], h[1]), pack_bf(h[2], h[3]));
    *(uint2*)(lo + i) = make_uint2(pack_bf(l[0], l[1]), pack_bf(l[2], l[3]));
}

__global__ void k_conv_split4(const float* __restrict__ tt, const float* __restrict__ cw,
                              const float* __restrict__ cb, bf16* __restrict__ thi,
                              bf16* __restrict__ tlo)
{
    long long idx = (long long)blockIdx.x * blockDim.x + threadIdx.x;
    if (idx >= (long long)2 * 4096 * 256) return;
    int d4 = (int)(idx & 255) * 4;
    long long bi = idx >> 8;
    int i = (int)(bi & 4095);
    int b = (int)(bi >> 12);
    const float* base = tt + (long long)b * 4096 * 1024 + d4;
    float4 acc = *(const float4*)(cb + d4);
#pragma unroll
    for (int k = 0; k < KSIZE; k++) {
        int src = i - (KSIZE - 1) + k;
        if (src >= 0) {
            float4 v = *(const float4*)(base + (long long)src * 1024);
            acc.x += v.x * cw[(d4 + 0) * KSIZE + k];
            acc.y += v.y * cw[(d4 + 1) * KSIZE + k];
            acc.z += v.z * cw[(d4 + 2) * KSIZE + k];
            acc.w += v.w * cw[(d4 + 3) * KSIZE + k];
        }
    }
    bf16 h[4], l[4];
    split_bf16(acc.x, h[0], l[0]); split_bf16(acc.y, h[1], l[1]);
    split_bf16(acc.z, h[2], l[2]); split_bf16(acc.w, h[3], l[3]);
    size_t o = ((size_t)b * 4096 + i) * 1024 + d4;
    *(uint2*)(thi + o) = make_uint2(pack_bf(h[0], h[1]), pack_bf(h[2], h[3]));
    *(uint2*)(tlo + o) = make_uint2(pack_bf(l[0], l[1]), pack_bf(l[2], l[3]));
}

// per-batch cumsum of dd -> wa hi/lo (vectorized x4); pointers pre-offset by batch
__global__ void k_wadp4b(const float* __restrict__ dd, const float* __restrict__ wdown,
                         bf16* __restrict__ whi, bf16* __restrict__ wlo)
{
    long long i = ((long long)blockIdx.x * blockDim.x + threadIdx.x) * 4;
    const long long DF = 1LL << 22;
    if (i >= DF) return;
    float4 acc = *(const float4*)(wdown + i);
#pragma unroll
    for (int j = 0; j < 16; j++) {
        bf16 h[4], l[4];
        split_bf16(acc.x, h[0], l[0]); split_bf16(acc.y, h[1], l[1]);
        split_bf16(acc.z, h[2], l[2]); split_bf16(acc.w, h[3], l[3]);
        size_t o = ((size_t)j << 22) + i;
        *(uint2*)(whi + o) = make_uint2(pack_bf(h[0], h[1]), pack_bf(h[2], h[3]));
        *(uint2*)(wlo + o) = make_uint2(pack_bf(l[0], l[1]), pack_bf(l[2], l[3]));
        if (j < 15) {
            float4 d4 = *(const float4*)(dd + ((size_t)j << 22) + i);
            acc.x += TTT_LR * d4.x; acc.y += TTT_LR * d4.y;
            acc.z += TTT_LR * d4.z; acc.w += TTT_LR * d4.w;
        }
    }
}

// per-batch reduce of 2 split-K partials
__global__ void k_reduce2b(const float* __restrict__ p0, const float* __restrict__ p1,
                           float* __restrict__ out)
{
    const long long N = 1LL << 22;   // one batch
    long long i = ((long long)blockIdx.x * blockDim.x + threadIdx.x) * 4;
    if (i >= N) return;
    float4 a = *(const float4*)(p0 + i);
    float4 b = *(const float4*)(p1 + i);
    *(float4*)(out + i) = make_float4(a.x + b.x, a.y + b.y, a.z + b.z, a.w + b.w);
}

// ================= launch =================
extern "C" void kernel_launch(void* const* d_in, const int* in_sizes, int n_in,
                              void* d_out, int out_size)
{
    const float* x     = (const float*)d_in[0];
    const float* tt    = (const float*)d_in[1];
    const float* wgu   = (const float*)d_in[2];
    const float* wdown = (const float*)d_in[3];
    const float* proj  = (const float*)d_in[4];
    const float* cw    = (const float*)d_in[5];
    const float* cb    = (const float*)d_in[6];
    float* out = (float*)d_out;

    bf16 *h_hi, *h_lo, *x_hi, *x_lo, *wgu_hi, *wgu_lo, *proj_hi, *proj_lo;
    bf16 *t_hi, *t_lo, *tp_hi, *tp_lo, *wa_hi, *wa_lo;
    float *dd, *p4;
    cudaGetSymbolAddress((void**)&h_hi, g_h_hi);     cudaGetSymbolAddress((void**)&h_lo, g_h_lo);
    cudaGetSymbolAddress((void**)&x_hi, g_x_hi);     cudaGetSymbolAddress((void**)&x_lo, g_x_lo);
    cudaGetSymbolAddress((void**)&wgu_hi, g_wgu_hi); cudaGetSymbolAddress((void**)&wgu_lo, g_wgu_lo);
    cudaGetSymbolAddress((void**)&proj_hi, g_proj_hi); cudaGetSymbolAddress((void**)&proj_lo, g_proj_lo);
    cudaGetSymbolAddress((void**)&t_hi, g_t_hi);     cudaGetSymbolAddress((void**)&t_lo, g_t_lo);
    cudaGetSymbolAddress((void**)&tp_hi, g_tp_hi);   cudaGetSymbolAddress((void**)&tp_lo, g_tp_lo);
    cudaGetSymbolAddress((void**)&wa_hi, g_wa_hi);   cudaGetSymbolAddress((void**)&wa_lo, g_wa_lo);
    cudaGetSymbolAddress((void**)&dd, g_dd);
    cudaGetSymbolAddress((void**)&p4, g_p4);

    static bool s_init = false;
    static cudaStream_t s1, s2;
    static cudaEvent_t evFork, evWgu, evSide, evW0, evW1, evG40, evR0;
    if (!s_init) {
        s_init = true;
        cudaStreamCreateWithFlags(&s1, cudaStreamNonBlocking);
        cudaStreamCreateWithFlags(&s2, cudaStreamNonBlocking);
        cudaEventCreateWithFlags(&evFork, cudaEventDisableTiming);
        cudaEventCreateWithFlags(&evWgu,  cudaEventDisableTiming);
        cudaEventCreateWithFlags(&evSide, cudaEventDisableTiming);
        cudaEventCreateWithFlags(&evW0,   cudaEventDisableTiming);
        cudaEventCreateWithFlags(&evW1,   cudaEventDisableTiming);
        cudaEventCreateWithFlags(&evG40,  cudaEventDisableTiming);
        cudaEventCreateWithFlags(&evR0,   cudaEventDisableTiming);
        cudaFuncSetAttribute(k_mma<0>, cudaFuncAttributeMaxDynamicSharedMemorySize, SMEM_NT);
        cudaFuncSetAttribute(k_mma<1>, cudaFuncAttributeMaxDynamicSharedMemorySize, SMEM_NT);
        cudaFuncSetAttribute(k_mma_tn, cudaFuncAttributeMaxDynamicSharedMemorySize, SMEM_TN);
        cudaFuncSetAttribute(k_mma_swiglu, cudaFuncAttributeMaxDynamicSharedMemorySize, SMEM_NT);
    }

    const long long DF   = 1LL << 22;             // 1024*4096
    const long long HB   = 4096LL * 4096;         // h batch stride
    const long long WAB  = 16LL * DF;             // wa batch stride
    const long long PB   = DF;                    // p4 batch stride
    const long long PS   = 2LL * DF;              // p4 split stride

    // fork
    cudaEventRecord(evFork, 0);
    cudaStreamWaitEvent(s1, evFork, 0);
    cudaStreamWaitEvent(s2, evFork, 0);

    // s2: wgu convert (feeds G1)
    k_convert4<<<(int)((8192LL * 1024 / 4 + 255) / 256), 256, 0, s2>>>(
        wgu, wgu_hi, wgu_lo, 8192LL * 1024);
    cudaEventRecord(evWgu, s2);

    // s1: conv -> proj convert -> G2 (1-term split)
    k_conv_split4<<<(int)((2LL * 4096 * 256 + 255) / 256), 256, 0, s1>>>(tt, cw, cb, t_hi, t_lo);
    k_convert4<<<(int)((1024LL * 1024 / 4 + 255) / 256), 256, 0, s1>>>(
        proj, proj_hi, proj_lo, 1024LL * 1024);
    k_mma<1><<<dim3(8, 30, 2), 256, SMEM_NT, s1>>>(
        t_hi, t_lo, 1024, proj_hi, proj_lo, 1024,
        nullptr, tp_hi, tp_lo, 1024, 1024, 1, /*terms=*/1,
        4096LL * 1024, 0, 0, 0, 3840LL * 1024, 0);
    cudaEventRecord(evSide, s1);

    // null: x convert -> (join wgu) -> G1 (3-term)
    k_convert4<<<(int)((8192LL * 1024 / 4 + 255) / 256), 256>>>(x, x_hi, x_lo, 8192LL * 1024);
    cudaStreamWaitEvent(0, evWgu, 0);
    k_mma_swiglu<<<dim3(64, 64, 1), 256, SMEM_NT>>>(x_hi, x_lo, wgu_hi, wgu_lo, h_hi, h_lo);

    // join side chain before G3
    cudaStreamWaitEvent(0, evSide, 0);

    // G3 (TN, BK=64, 1-term), full-width z=30
    k_mma_tn<<<dim3(32, 8, 30), 256, SMEM_TN>>>(
        tp_hi, tp_lo, 1024, h_hi, h_lo, 4096, dd, 4096, 256, 15, /*terms=*/1,
        3840LL * 1024, 256LL * 1024, 4096LL * 4096, 256LL * 4096,
        15LL * 1024 * 4096, 1024LL * 4096);

    // wadp batch 0 (null), then fork: G4(b0) on null || wadp batch 1 on s1
    k_wadp4b<<<(int)((DF / 4 + 255) / 256), 256>>>(dd, wdown, wa_hi, wa_lo);
    cudaEventRecord(evW0, 0);
    cudaStreamWaitEvent(s1, evW0, 0);
    k_wadp4b<<<(int)((DF / 4 + 255) / 256), 256, 0, s1>>>(
        dd + 15 * DF, wdown, wa_hi + WAB, wa_lo + WAB);
    cudaEventRecord(evW1, s1);

    // G4 batch 0 (split-K=2, 3-term)
    k_mma<0><<<dim3(8, 2, 32), 256, SMEM_NT>>>(
        h_hi, h_lo, 4096, wa_hi, wa_lo, 4096,
        p4, nullptr, nullptr, 1024, 2048, 2, /*terms=*/3,
        256LL * 4096, 2048, DF, 2048,
        256LL * 1024, PS);
    cudaEventRecord(evG40, 0);

    // reduce(b0) on s2 concurrent with G4(b1)
    cudaStreamWaitEvent(s2, evG40, 0);
    k_reduce2b<<<(int)((DF / 4 + 255) / 256), 256, 0, s2>>>(p4, p4 + PS, out);
    cudaEventRecord(evR0, s2);

    // G4 batch 1 after wadp(b1)
    cudaStreamWaitEvent(0, evW1, 0);
    k_mma<0><<<dim3(8, 2, 32), 256, SMEM_NT>>>(
        h_hi + HB, h_lo + HB, 4096, wa_hi + WAB, wa_lo + WAB, 4096,
        p4 + PB, nullptr, nullptr, 1024, 2048, 2, /*terms=*/3,
        256LL * 4096, 2048, DF, 2048,
        256LL * 1024, PS);

    // reduce(b1) on null, then join reduce(b0)
    k_reduce2b<<<(int)((DF / 4 + 255) / 256), 256>>>(p4 + PB, p4 + PS + PB, out + DF);
    cudaStreamWaitEvent(0, evR0, 0);
}

// round 16
// speedup vs baseline: 1.3693x; 1.3263x over previous
#include <cuda_runtime.h>
#include <cuda_fp16.h>
#include <cstdint>

#define TTT_LR  0.01f
#define KSIZE   5

// NT tiling: 128x128x64, 8 warps of 64x32, occ 2
#define BK 64
#define NPITCH 144
#define NA_SZ (128 * NPITCH)
#define NST (2 * NA_SZ)
#define STAGES 3
#define SMEM_NT (STAGES * NST)        // 110592

// TN tiling (G3): [k][mn], BK=64
#define ATP 272
#define A_SZT (64 * ATP)
#define ST_SZT (2 * A_SZT)
#define SMEM_TN (STAGES * ST_SZT)     // 104448

typedef __half f16;

// ================= device scratch =================
__device__ __align__(16) f16   g_h_hi [(size_t)8192 * 4096];
__device__ __align__(16) f16   g_h_lo [(size_t)8192 * 4096];
__device__ __align__(16) f16   g_x_hi [(size_t)8192 * 1024];
__device__ __align__(16) f16   g_x_lo [(size_t)8192 * 1024];
__device__ __align__(16) f16   g_wgu_hi[(size_t)8192 * 1024];
__device__ __align__(16) f16   g_wgu_lo[(size_t)8192 * 1024];
__device__ __align__(16) f16   g_proj_hi[(size_t)1024 * 1024];
__device__ __align__(16) f16   g_proj_lo[(size_t)1024 * 1024];
__device__ __align__(16) f16   g_t_hi [(size_t)2 * 4096 * 1024];
__device__ __align__(16) f16   g_t_lo [(size_t)2 * 4096 * 1024];
__device__ __align__(16) f16   g_tp_hi[(size_t)2 * 3840 * 1024];
__device__ __align__(16) f16   g_tp_lo[(size_t)2 * 3840 * 1024];
__device__ __align__(16) float g_dd   [(size_t)2 * 15 * 1024 * 4096];
__device__ __align__(16) f16   g_wa_hi[(size_t)2 * 16 * 1024 * 4096];
__device__ __align__(16) f16   g_wa_lo[(size_t)2 * 16 * 1024 * 4096];
__device__ __align__(16) float g_p4   [(size_t)4 * 2 * 4096 * 1024];  // partials

// ================= PTX helpers =================
__device__ __forceinline__ uint32_t smem_u32(const void* p) {
    uint32_t a;
    asm("{ .reg .u64 t; cvta.to.shared.u64 t, %1; cvt.u32.u64 %0, t; }" : "=r"(a) : "l"(p));
    return a;
}
__device__ __forceinline__ void cp_async16(uint32_t sdst, const void* gsrc) {
    asm volatile("cp.async.cg.shared.global [%0], [%1], 16;" :: "r"(sdst), "l"(gsrc) : "memory");
}
__device__ __forceinline__ void cp_commit() {
    asm volatile("cp.async.commit_group;" ::: "memory");
}
__device__ __forceinline__ void ldm_x4(uint32_t addr, uint32_t& r0, uint32_t& r1,
                                       uint32_t& r2, uint32_t& r3) {
    asm volatile("ldmatrix.sync.aligned.m8n8.x4.shared.b16 {%0,%1,%2,%3}, [%4];"
                 : "=r"(r0), "=r"(r1), "=r"(r2), "=r"(r3) : "r"(addr));
}
__device__ __forceinline__ void ldm_x4_t(uint32_t addr, uint32_t& r0, uint32_t& r1,
                                         uint32_t& r2, uint32_t& r3) {
    asm volatile("ldmatrix.sync.aligned.m8n8.x4.trans.shared.b16 {%0,%1,%2,%3}, [%4];"
                 : "=r"(r0), "=r"(r1), "=r"(r2), "=r"(r3) : "r"(addr));
}
__device__ __forceinline__ void mma16816(float* c, const uint32_t* a, uint32_t b0, uint32_t b1) {
    asm volatile("mma.sync.aligned.m16n8k16.row.col.f32.f16.f16.f32 "
                 "{%0,%1,%2,%3}, {%4,%5,%6,%7}, {%8,%9}, {%0,%1,%2,%3};"
                 : "+f"(c[0]), "+f"(c[1]), "+f"(c[2]), "+f"(c[3])
                 : "r"(a[0]), "r"(a[1]), "r"(a[2]), "r"(a[3]), "r"(b0), "r"(b1));
}
__device__ __forceinline__ void split_f16(float v, f16& hi, f16& lo) {
    hi = __float2half_rn(v);
    lo = __float2half_rn(v - __half2float(hi));
}
__device__ __forceinline__ uint32_t pack_hf(f16 a, f16 b) {
    return (uint32_t)__half_as_ushort(a) | ((uint32_t)__half_as_ushort(b) << 16);
}

// ================= NT GEMM 128x128x64, fp16 hi/lo multi-pass split =================
// terms: 3 = Ahi*Bhi + Ahi*Blo + Alo*Bhi ; 2 = Ahi*Bhi + Ahi*Blo ; 1 = Ahi*Bhi
template <int SPLIT_OUT>
__global__ __launch_bounds__(256, 2) void k_mma(
    const f16* __restrict__ Ahi, const f16* __restrict__ Alo, long long lda,
    const f16* __restrict__ Bhi, const f16* __restrict__ Blo, long long ldb,
    float* __restrict__ C, f16* __restrict__ Chi, f16* __restrict__ Clo,
    long long ldc, int K, int Z2, int terms,
    long long sA1, long long sA2, long long sB1, long long sB2,
    long long sC1, long long sC2)
{
    extern __shared__ char smem[];
    const uint32_t sb = smem_u32(smem);
    const int tid = threadIdx.x;
    const int lane = tid & 31;
    const int warp = tid >> 5;
    const int wm = warp >> 2;
    const int wn = warp & 3;

    const int z = blockIdx.z, z1 = z / Z2, z2 = z % Z2;
    const long long aoff = (long long)z1 * sA1 + (long long)z2 * sA2 + (long long)blockIdx.y * 128 * lda;
    const long long boff = (long long)z1 * sB1 + (long long)z2 * sB2 + (long long)blockIdx.x * 128 * ldb;
    Ahi += aoff; Alo += aoff;
    Bhi += boff; Blo += boff;
    const long long coff = (long long)z1 * sC1 + (long long)z2 * sC2
                         + (long long)blockIdx.y * 128 * ldc + (long long)blockIdx.x * 128;

    const int KI = K / BK;
    const int total = terms * KI;

    float acc[4][4][4];
#pragma unroll
    for (int i = 0; i < 4; i++)
#pragma unroll
        for (int n = 0; n < 4; n++)
#pragma unroll
            for (int r = 0; r < 4; r++) acc[i][n][r] = 0.f;

    const int lrow = tid >> 3;
    const int lko  = tid & 7;

    auto issue_load = [&](int it) {
        const int seg = (it >= 2 * KI) ? 2 : (it >= KI ? 1 : 0);
        const f16* Ag = (seg == 2) ? Alo : Ahi;
        const f16* Bg = (seg == 1) ? Blo : Bhi;
        const int kk = (it - seg * KI) * BK;
        const uint32_t sa = sb + (it % STAGES) * NST;
        const uint32_t sB = sa + NA_SZ;
#pragma unroll
        for (int q = 0; q < 4; q++) {
            const int row = lrow + q * 32;
            const uint32_t so = (uint32_t)row * NPITCH + lko * 16;
            cp_async16(sa + so, Ag + (size_t)row * lda + kk + lko * 8);
            cp_async16(sB + so, Bg + (size_t)row * ldb + kk + lko * 8);
        }
    };

#pragma unroll
    for (int s = 0; s < STAGES - 1; s++) {
        if (s < total) issue_load(s);
        cp_commit();
    }

    const uint32_t aRow = (uint32_t)(wm * 64 + (lane & 15));
    const uint32_t bRow = (uint32_t)(wn * 32 + (lane & 15));
    const uint32_t kByte = (uint32_t)((lane >> 4) * 16);

    for (int it = 0; it < total; ++it) {
        asm volatile("cp.async.wait_group %0;" :: "n"(STAGES - 2) : "memory");
        __syncthreads();
        const int nx = it + STAGES - 1;
        if (nx < total) issue_load(nx);
        cp_commit();

        const uint32_t sa = sb + (it % STAGES) * NST;
        const uint32_t sB = sa + NA_SZ;
#pragma unroll
        for (int k16 = 0; k16 < 4; k16++) {
            uint32_t a[4][4], b[2][4];
#pragma unroll
            for (int i = 0; i < 4; i++)
                ldm_x4(sa + (aRow + i * 16) * NPITCH + kByte + k16 * 32,
                       a[i][0], a[i][1], a[i][2], a[i][3]);
#pragma unroll
            for (int j = 0; j < 2; j++)
                ldm_x4(sB + (bRow + j * 16) * NPITCH + kByte + k16 * 32,
                       b[j][0], b[j][1], b[j][2], b[j][3]);
#pragma unroll
            for (int i = 0; i < 4; i++) {
#pragma unroll
                for (int n = 0; n < 4; n++) {
                    const int j = n >> 1, h = n & 1;
                    mma16816(acc[i][n], a[i], b[j][h], b[j][h + 2]);
                }
            }
        }
    }

    const int g = lane >> 2, t2 = (lane & 3) * 2;
#pragma unroll
    for (int i = 0; i < 4; i++) {
        const int r = wm * 64 + i * 16 + g;
#pragma unroll
        for (int n = 0; n < 4; n++) {
            const int cc = wn * 32 + (n >> 1) * 16 + (n & 1) * 8 + t2;
            if (SPLIT_OUT) {
                f16 h0, l0, h1, l1;
                split_f16(acc[i][n][0], h0, l0); split_f16(acc[i][n][1], h1, l1);
                *(uint32_t*)(Chi + coff + (size_t)r * ldc + cc) = pack_hf(h0, h1);
                *(uint32_t*)(Clo + coff + (size_t)r * ldc + cc) = pack_hf(l0, l1);
                split_f16(acc[i][n][2], h0, l0); split_f16(acc[i][n][3], h1, l1);
                *(uint32_t*)(Chi + coff + (size_t)(r + 8) * ldc + cc) = pack_hf(h0, h1);
                *(uint32_t*)(Clo + coff + (size_t)(r + 8) * ldc + cc) = pack_hf(l0, l1);
            } else {
                *(float2*)&C[coff + (size_t)r * ldc + cc]       = make_float2(acc[i][n][0], acc[i][n][1]);
                *(float2*)&C[coff + (size_t)(r + 8) * ldc + cc] = make_float2(acc[i][n][2], acc[i][n][3]);
            }
        }
    }
}

// ================= TN GEMM 128x128x64: C[m,n] = sum_k A[k,m]*B[k,n] =================
__global__ __launch_bounds__(256, 2) void k_mma_tn(
    const f16* __restrict__ Ahi, const f16* __restrict__ Alo, long long lda,
    const f16* __restrict__ Bhi, const f16* __restrict__ Blo, long long ldb,
    float* __restrict__ C, long long ldc, int K, int Z2, int terms,
    long long sA1, long long sA2, long long sB1, long long sB2,
    long long sC1, long long sC2)
{
    extern __shared__ char smem[];
    const uint32_t sb = smem_u32(smem);
    const int tid = threadIdx.x;
    const int lane = tid & 31;
    const int warp = tid >> 5;
    const int wm = warp >> 2;
    const int wn = warp & 3;

    const int z = blockIdx.z, z1 = z / Z2, z2 = z % Z2;
    const long long aoff = (long long)z1 * sA1 + (long long)z2 * sA2 + (long long)blockIdx.y * 128;
    const long long boff = (long long)z1 * sB1 + (long long)z2 * sB2 + (long long)blockIdx.x * 128;
    Ahi += aoff; Alo += aoff;
    Bhi += boff; Blo += boff;
    C   += (long long)z1 * sC1 + (long long)z2 * sC2
         + (long long)blockIdx.y * 128 * ldc + (long long)blockIdx.x * 128;

    const int KI = K / 64;
    const int total = terms * KI;

    float acc[4][4][4];
#pragma unroll
    for (int i = 0; i < 4; i++)
#pragma unroll
        for (int n = 0; n < 4; n++)
#pragma unroll
            for (int r = 0; r < 4; r++) acc[i][n][r] = 0.f;

    auto issue_load = [&](int it) {
        const int seg = (it >= 2 * KI) ? 2 : (it >= KI ? 1 : 0);
        const f16* Ag = (seg == 2) ? Alo : Ahi;
        const f16* Bg = (seg == 1) ? Blo : Bhi;
        const int kk = (it - seg * KI) * 64;
        const uint32_t sa = sb + (it % STAGES) * ST_SZT;
        const uint32_t sB = sa + A_SZT;
#pragma unroll
        for (int q = 0; q < 4; q++) {
            const int c = tid + q * 256;
            const int row = c >> 4, col = c & 15;
            const uint32_t so = (uint32_t)row * ATP + col * 16;
            cp_async16(sa + so, Ag + (size_t)(kk + row) * lda + col * 8);
            cp_async16(sB + so, Bg + (size_t)(kk + row) * ldb + col * 8);
        }
    };

#pragma unroll
    for (int s = 0; s < STAGES - 1; s++) {
        if (s < total) issue_load(s);
        cp_commit();
    }

    const uint32_t aK = (lane & 7) + ((lane >> 4) & 1) * 8;
    const uint32_t aM = (uint32_t)(wm * 64) * 2 + ((lane >> 3) & 1) * 16;
    const uint32_t bK = (lane & 7) + ((lane >> 3) & 1) * 8;
    const uint32_t bN = (uint32_t)(wn * 32) * 2 + ((lane >> 4) & 1) * 16;

    for (int it = 0; it < total; ++it) {
        asm volatile("cp.async.wait_group %0;" :: "n"(STAGES - 2) : "memory");
        __syncthreads();
        const int nx = it + STAGES - 1;
        if (nx < total) issue_load(nx);
        cp_commit();

        const uint32_t sa = sb + (it % STAGES) * ST_SZT;
        const uint32_t sB = sa + A_SZT;
#pragma unroll
        for (int k16 = 0; k16 < 4; k16++) {
            uint32_t a[4][4], b[2][4];
#pragma unroll
            for (int i = 0; i < 4; i++)
                ldm_x4_t(sa + (k16 * 16 + aK) * ATP + aM + i * 32,
                         a[i][0], a[i][1], a[i][2], a[i][3]);
#pragma unroll
            for (int gidx = 0; gidx < 2; gidx++)
                ldm_x4_t(sB + (k16 * 16 + bK) * ATP + bN + gidx * 32,
                         b[gidx][0], b[gidx][1], b[gidx][2], b[gidx][3]);
#pragma unroll
            for (int i = 0; i < 4; i++) {
#pragma unroll
                for (int n = 0; n < 4; n++) {
                    const int gr = n >> 1, h = (n & 1) * 2;
                    mma16816(acc[i][n], a[i], b[gr][h], b[gr][h + 1]);
                }
            }
        }
    }

    const int g = lane >> 2, t2 = (lane & 3) * 2;
#pragma unroll
    for (int i = 0; i < 4; i++) {
        const int r = wm * 64 + i * 16 + g;
#pragma unroll
        for (int n = 0; n < 4; n++) {
            const int cc = wn * 32 + (n >> 1) * 16 + (n & 1) * 8 + t2;
            *(float2*)&C[(size_t)r * ldc + cc]       = make_float2(acc[i][n][0], acc[i][n][1]);
            *(float2*)&C[(size_t)(r + 8) * ldc + cc] = make_float2(acc[i][n][2], acc[i][n][3]);
        }
    }
}

// ================= fused G1 + SwiGLU (128 rows x 64 f-cols, BK=64, 2-term fp16) =================
__global__ __launch_bounds__(256, 2) void k_mma_swiglu(
    const f16* __restrict__ Ahi, const f16* __restrict__ Alo,
    const f16* __restrict__ Bhi, const f16* __restrict__ Blo,
    f16* __restrict__ Hhi, f16* __restrict__ Hlo)
{
    extern __shared__ char smem[];
    const uint32_t sb = smem_u32(smem);
    const int tid = threadIdx.x;
    const int lane = tid & 31;
    const int warp = tid >> 5;
    const int wm = warp >> 2;
    const int wn = warp & 3;

    int l = blockIdx.y * gridDim.x + blockIdx.x;
    const int per = 8 * gridDim.x;
    const int grp = l / per, rem = l % per;
    const int by = grp * 8 + (rem & 7);
    const int bx = rem >> 3;

    const int KI = 16;
    const int total = 32;   // 2-term fp16

    float accg[4][2][4], accu[4][2][4];
#pragma unroll
    for (int i = 0; i < 4; i++)
#pragma unroll
        for (int n = 0; n < 2; n++)
#pragma unroll
            for (int r = 0; r < 4; r++) { accg[i][n][r] = 0.f; accu[i][n][r] = 0.f; }

    const int lrow = tid >> 3;
    const int lko  = tid & 7;

    auto issue_load = [&](int it) {
        const int seg = (it >= 2 * KI) ? 2 : (it >= KI ? 1 : 0);
        const f16* Ag = (seg == 2) ? Alo : Ahi;
        const f16* Bg = (seg == 1) ? Blo : Bhi;
        const int kk = (it - seg * KI) * BK;
        const uint32_t sa = sb + (it % STAGES) * NST;
        const uint32_t sB = sa + NA_SZ;
#pragma unroll
        for (int q = 0; q < 4; q++) {
            const int row = lrow + q * 32;
            const uint32_t so = (uint32_t)row * NPITCH + lko * 16;
            cp_async16(sa + so, Ag + (size_t)(by * 128 + row) * 1024 + kk + lko * 8);
            const size_t grow = (row < 64) ? (size_t)(bx * 64 + row)
                                           : (size_t)(4096 + bx * 64 + row - 64);
            cp_async16(sB + so, Bg + grow * 1024 + kk + lko * 8);
        }
    };

#pragma unroll
    for (int s = 0; s < STAGES - 1; s++) { issue_load(s); cp_commit(); }

    const uint32_t aRow = (uint32_t)(wm * 64 + (lane & 15));
    const uint32_t gRow = (uint32_t)(wn * 16 + (lane & 15));
    const uint32_t uRow = gRow + 64;
    const uint32_t kByte = (uint32_t)((lane >> 4) * 16);

    for (int it = 0; it < total; ++it) {
        asm volatile("cp.async.wait_group %0;" :: "n"(STAGES - 2) : "memory");
        __syncthreads();
        const int nx = it + STAGES - 1;
        if (nx < total) issue_load(nx);
        cp_commit();

        const uint32_t sa = sb + (it % STAGES) * NST;
        const uint32_t sB = sa + NA_SZ;
#pragma unroll
        for (int k16 = 0; k16 < 4; k16++) {
            uint32_t a[4][4], bg[4], bu[4];
#pragma unroll
            for (int i = 0; i < 4; i++)
                ldm_x4(sa + (aRow + i * 16) * NPITCH + kByte + k16 * 32,
                       a[i][0], a[i][1], a[i][2], a[i][3]);
            ldm_x4(sB + gRow * NPITCH + kByte + k16 * 32, bg[0], bg[1], bg[2], bg[3]);
            ldm_x4(sB + uRow * NPITCH + kByte + k16 * 32, bu[0], bu[1], bu[2], bu[3]);
#pragma unroll
            for (int i = 0; i < 4; i++) {
#pragma unroll
                for (int n = 0; n < 2; n++) {
                    mma16816(accg[i][n], a[i], bg[n], bg[n + 2]);
                    mma16816(accu[i][n], a[i], bu[n], bu[n + 2]);
                }
            }
        }
    }

    const int g = lane >> 2, t2 = (lane & 3) * 2;
#pragma unroll
    for (int i = 0; i < 4; i++) {
#pragma unroll
        for (int n = 0; n < 2; n++) {
            const int col = bx * 64 + wn * 16 + n * 8 + t2;
#pragma unroll
            for (int half = 0; half < 2; half++) {
                const size_t row = (size_t)by * 128 + wm * 64 + i * 16 + g + half * 8;
                float g0 = accg[i][n][half * 2 + 0], g1 = accg[i][n][half * 2 + 1];
                float u0 = accu[i][n][half * 2 + 0], u1 = accu[i][n][half * 2 + 1];
                float h0 = g0 / (1.0f + expf(-g0)) * u0;
                float h1 = g1 / (1.0f + expf(-g1)) * u1;
                f16 h0h, h0l, h1h, h1l;
                split_f16(h0, h0h, h0l); split_f16(h1, h1h, h1l);
                *(uint32_t*)(Hhi + row * 4096 + col) = pack_hf(h0h, h1h);
                *(uint32_t*)(Hlo + row * 4096 + col) = pack_hf(h0l, h1l);
            }
        }
    }
}

// ================= elementwise kernels =================
__global__ void k_convert4(const float* __restrict__ in, f16* __restrict__ hi,
                           f16* __restrict__ lo, long long n)
{
    long long i = ((long long)blockIdx.x * blockDim.x + threadIdx.x) * 4;
    if (i >= n) return;
    float4 v = *(const float4*)(in + i);
    f16 h[4], l[4];
    split_f16(v.x, h[0], l[0]); split_f16(v.y, h[1], l[1]);
    split_f16(v.z, h[2], l[2]); split_f16(v.w, h[3], l[3]);
    *(uint2*)(hi + i) = make_uint2(pack_hf(h[0], h[1]), pack_hf(h[2], h[3]));
    *(uint2*)(lo + i) = make_uint2(pack_hf(l[0], l[1]), pack_hf(l[2], l[3]));
}

__global__ void k_conv_split4(const float* __restrict__ tt, const float* __restrict__ cw,
                              const float* __restrict__ cb, f16* __restrict__ thi,
                              f16* __restrict__ tlo)
{
    long long idx = (long long)blockIdx.x * blockDim.x + threadIdx.x;
    if (idx >= (long long)2 * 4096 * 256) return;
    int d4 = (int)(idx & 255) * 4;
    long long bi = idx >> 8;
    int i = (int)(bi & 4095);
    int b = (int)(bi >> 12);
    const float* base = tt + (long long)b * 4096 * 1024 + d4;
    float4 acc = *(const float4*)(cb + d4);
#pragma unroll
    for (int k = 0; k < KSIZE; k++) {
        int src = i - (KSIZE - 1) + k;
        if (src >= 0) {
            float4 v = *(const float4*)(base + (long long)src * 1024);
            acc.x += v.x * cw[(d4 + 0) * KSIZE + k];
            acc.y += v.y * cw[(d4 + 1) * KSIZE + k];
            acc.z += v.z * cw[(d4 + 2) * KSIZE + k];
            acc.w += v.w * cw[(d4 + 3) * KSIZE + k];
        }
    }
    f16 h[4], l[4];
    split_f16(acc.x, h[0], l[0]); split_f16(acc.y, h[1], l[1]);
    split_f16(acc.z, h[2], l[2]); split_f16(acc.w, h[3], l[3]);
    size_t o = ((size_t)b * 4096 + i) * 1024 + d4;
    *(uint2*)(thi + o) = make_uint2(pack_hf(h[0], h[1]), pack_hf(h[2], h[3]));
    *(uint2*)(tlo + o) = make_uint2(pack_hf(l[0], l[1]), pack_hf(l[2], l[3]));
}

// per-batch cumsum of dd -> wa hi/lo (vectorized x4); pointers pre-offset by batch
__global__ void k_wadp4b(const float* __restrict__ dd, const float* __restrict__ wdown,
                         f16* __restrict__ whi, f16* __restrict__ wlo)
{
    long long i = ((long long)blockIdx.x * blockDim.x + threadIdx.x) * 4;
    const long long DF = 1LL << 22;
    if (i >= DF) return;
    float4 acc = *(const float4*)(wdown + i);
#pragma unroll
    for (int j = 0; j < 16; j++) {
        f16 h[4], l[4];
        split_f16(acc.x, h[0], l[0]); split_f16(acc.y, h[1], l[1]);
        split_f16(acc.z, h[2], l[2]); split_f16(acc.w, h[3], l[3]);
        size_t o = ((size_t)j << 22) + i;
        *(uint2*)(whi + o) = make_uint2(pack_hf(h[0], h[1]), pack_hf(h[2], h[3]));
        *(uint2*)(wlo + o) = make_uint2(pack_hf(l[0], l[1]), pack_hf(l[2], l[3]));
        if (j < 15) {
            float4 d4 = *(const float4*)(dd + ((size_t)j << 22) + i);
            acc.x += TTT_LR * d4.x; acc.y += TTT_LR * d4.y;
            acc.z += TTT_LR * d4.z; acc.w += TTT_LR * d4.w;
        }
    }
}

// per-batch reduce of 2 split-K partials
__global__ void k_reduce2b(const float* __restrict__ p0, const float* __restrict__ p1,
                           float* __restrict__ out)
{
    const long long N = 1LL << 22;   // one batch
    long long i = ((long long)blockIdx.x * blockDim.x + threadIdx.x) * 4;
    if (i >= N) return;
    float4 a = *(const float4*)(p0 + i);
    float4 b = *(const float4*)(p1 + i);
    *(float4*)(out + i) = make_float4(a.x + b.x, a.y + b.y, a.z + b.z, a.w + b.w);
}

// ================= launch =================
extern "C" void kernel_launch(void* const* d_in, const int* in_sizes, int n_in,
                              void* d_out, int out_size)
{
    const float* x     = (const float*)d_in[0];
    const float* tt    = (const float*)d_in[1];
    const float* wgu   = (const float*)d_in[2];
    const float* wdown = (const float*)d_in[3];
    const float* proj  = (const float*)d_in[4];
    const float* cw    = (const float*)d_in[5];
    const float* cb    = (const float*)d_in[6];
    float* out = (float*)d_out;

    f16 *h_hi, *h_lo, *x_hi, *x_lo, *wgu_hi, *wgu_lo, *proj_hi, *proj_lo;
    f16 *t_hi, *t_lo, *tp_hi, *tp_lo, *wa_hi, *wa_lo;
    float *dd, *p4;
    cudaGetSymbolAddress((void**)&h_hi, g_h_hi);     cudaGetSymbolAddress((void**)&h_lo, g_h_lo);
    cudaGetSymbolAddress((void**)&x_hi, g_x_hi);     cudaGetSymbolAddress((void**)&x_lo, g_x_lo);
    cudaGetSymbolAddress((void**)&wgu_hi, g_wgu_hi); cudaGetSymbolAddress((void**)&wgu_lo, g_wgu_lo);
    cudaGetSymbolAddress((void**)&proj_hi, g_proj_hi); cudaGetSymbolAddress((void**)&proj_lo, g_proj_lo);
    cudaGetSymbolAddress((void**)&t_hi, g_t_hi);     cudaGetSymbolAddress((void**)&t_lo, g_t_lo);
    cudaGetSymbolAddress((void**)&tp_hi, g_tp_hi);   cudaGetSymbolAddress((void**)&tp_lo, g_tp_lo);
    cudaGetSymbolAddress((void**)&wa_hi, g_wa_hi);   cudaGetSymbolAddress((void**)&wa_lo, g_wa_lo);
    cudaGetSymbolAddress((void**)&dd, g_dd);
    cudaGetSymbolAddress((void**)&p4, g_p4);

    static bool s_init = false;
    static cudaStream_t s1, s2;
    static cudaEvent_t evFork, evWgu, evSide, evW0, evW1, evG40, evR0;
    if (!s_init) {
        s_init = true;
        cudaStreamCreateWithFlags(&s1, cudaStreamNonBlocking);
        cudaStreamCreateWithFlags(&s2, cudaStreamNonBlocking);
        cudaEventCreateWithFlags(&evFork, cudaEventDisableTiming);
        cudaEventCreateWithFlags(&evWgu,  cudaEventDisableTiming);
        cudaEventCreateWithFlags(&evSide, cudaEventDisableTiming);
        cudaEventCreateWithFlags(&evW0,   cudaEventDisableTiming);
        cudaEventCreateWithFlags(&evW1,   cudaEventDisableTiming);
        cudaEventCreateWithFlags(&evG40,  cudaEventDisableTiming);
        cudaEventCreateWithFlags(&evR0,   cudaEventDisableTiming);
        cudaFuncSetAttribute(k_mma<0>, cudaFuncAttributeMaxDynamicSharedMemorySize, SMEM_NT);
        cudaFuncSetAttribute(k_mma<1>, cudaFuncAttributeMaxDynamicSharedMemorySize, SMEM_NT);
        cudaFuncSetAttribute(k_mma_tn, cudaFuncAttributeMaxDynamicSharedMemorySize, SMEM_TN);
        cudaFuncSetAttribute(k_mma_swiglu, cudaFuncAttributeMaxDynamicSharedMemorySize, SMEM_NT);
    }

    const long long DF   = 1LL << 22;             // 1024*4096
    const long long HB   = 4096LL * 4096;         // h batch stride
    const long long WAB  = 16LL * DF;             // wa batch stride
    const long long PB   = DF;                    // p4 batch stride
    const long long PS   = 2LL * DF;              // p4 split stride

    // fork
    cudaEventRecord(evFork, 0);
    cudaStreamWaitEvent(s1, evFork, 0);
    cudaStreamWaitEvent(s2, evFork, 0);

    // s2: wgu convert (feeds G1)
    k_convert4<<<(int)((8192LL * 1024 / 4 + 255) / 256), 256, 0, s2>>>(
        wgu, wgu_hi, wgu_lo, 8192LL * 1024);
    cudaEventRecord(evWgu, s2);

    // s1: conv -> proj convert -> G2 (1-term fp16)
    k_conv_split4<<<(int)((2LL * 4096 * 256 + 255) / 256), 256, 0, s1>>>(tt, cw, cb, t_hi, t_lo);
    k_convert4<<<(int)((1024LL * 1024 / 4 + 255) / 256), 256, 0, s1>>>(
        proj, proj_hi, proj_lo, 1024LL * 1024);
    k_mma<1><<<dim3(8, 30, 2), 256, SMEM_NT, s1>>>(
        t_hi, t_lo, 1024, proj_hi, proj_lo, 1024,
        nullptr, tp_hi, tp_lo, 1024, 1024, 1, /*terms=*/1,
        4096LL * 1024, 0, 0, 0, 3840LL * 1024, 0);
    cudaEventRecord(evSide, s1);

    // null: x convert -> (join wgu) -> G1 (2-term fp16)
    k_convert4<<<(int)((8192LL * 1024 / 4 + 255) / 256), 256>>>(x, x_hi, x_lo, 8192LL * 1024);
    cudaStreamWaitEvent(0, evWgu, 0);
    k_mma_swiglu<<<dim3(64, 64, 1), 256, SMEM_NT>>>(x_hi, x_lo, wgu_hi, wgu_lo, h_hi, h_lo);

    // join side chain before G3
    cudaStreamWaitEvent(0, evSide, 0);

    // G3 (TN, BK=64, 1-term fp16), full-width z=30
    k_mma_tn<<<dim3(32, 8, 30), 256, SMEM_TN>>>(
        tp_hi, tp_lo, 1024, h_hi, h_lo, 4096, dd, 4096, 256, 15, /*terms=*/1,
        3840LL * 1024, 256LL * 1024, 4096LL * 4096, 256LL * 4096,
        15LL * 1024 * 4096, 1024LL * 4096);

    // wadp batch 0 (null), then fork: G4(b0) on null || wadp batch 1 on s1
    k_wadp4b<<<(int)((DF / 4 + 255) / 256), 256>>>(dd, wdown, wa_hi, wa_lo);
    cudaEventRecord(evW0, 0);
    cudaStreamWaitEvent(s1, evW0, 0);
    k_wadp4b<<<(int)((DF / 4 + 255) / 256), 256, 0, s1>>>(
        dd + 15 * DF, wdown, wa_hi + WAB, wa_lo + WAB);
    cudaEventRecord(evW1, s1);

    // G4 batch 0 (split-K=2, 2-term fp16)
    k_mma<0><<<dim3(8, 2, 32), 256, SMEM_NT>>>(
        h_hi, h_lo, 4096, wa_hi, wa_lo, 4096,
        p4, nullptr, nullptr, 1024, 2048, 2, /*terms=*/2,
        256LL * 4096, 2048, DF, 2048,
        256LL * 1024, PS);
    cudaEventRecord(evG40, 0);

    // reduce(b0) on s2 concurrent with G4(b1)
    cudaStreamWaitEvent(s2, evG40, 0);
    k_reduce2b<<<(int)((DF / 4 + 255) / 256), 256, 0, s2>>>(p4, p4 + PS, out);
    cudaEventRecord(evR0, s2);

    // G4 batch 1 after wadp(b1)
    cudaStreamWaitEvent(0, evW1, 0);
    k_mma<0><<<dim3(8, 2, 32), 256, SMEM_NT>>>(
        h_hi + HB, h_lo + HB, 4096, wa_hi + WAB, wa_lo + WAB, 4096,
        p4 + PB, nullptr, nullptr, 1024, 2048, 2, /*terms=*/2,
        256LL * 4096, 2048, DF, 2048,
        256LL * 1024, PS);

    // reduce(b1) on null, then join reduce(b0)
    k_reduce2b<<<(int)((DF / 4 + 255) / 256), 256>>>(p4 + PB, p4 + PS + PB, out + DF);
    cudaStreamWaitEvent(0, evR0, 0);
}

// round 17
// speedup vs baseline: 2.2235x; 1.6238x over previous
#include <cuda_runtime.h>
#include <cuda_fp16.h>
#include <cstdint>

#define TTT_LR  0.01f
#define KSIZE   5

// NT tiling: 128x128x64, 8 warps of 64x32, occ 2
#define BK 64
#define NPITCH 144
#define NA_SZ (128 * NPITCH)
#define NST (2 * NA_SZ)
#define STAGES 3
#define SMEM_NT (STAGES * NST)        // 110592

// TN tiling (G3): [k][mn], BK=64
#define ATP 272
#define A_SZT (64 * ATP)
#define ST_SZT (2 * A_SZT)
#define SMEM_TN (STAGES * ST_SZT)     // 104448

typedef __half f16;

// ================= device scratch (pure fp16, hi-only) =================
__device__ __align__(16) f16   g_h   [(size_t)8192 * 4096];
__device__ __align__(16) f16   g_x   [(size_t)8192 * 1024];
__device__ __align__(16) f16   g_wgu [(size_t)8192 * 1024];
__device__ __align__(16) f16   g_proj[(size_t)1024 * 1024];
__device__ __align__(16) f16   g_t   [(size_t)2 * 4096 * 1024];
__device__ __align__(16) f16   g_tp  [(size_t)2 * 3840 * 1024];
__device__ __align__(16) float g_dd  [(size_t)2 * 15 * 1024 * 4096];
__device__ __align__(16) f16   g_wa  [(size_t)2 * 16 * 1024 * 4096];
__device__ __align__(16) float g_p4  [(size_t)4 * 2 * 4096 * 1024];   // partials

// ================= PTX helpers =================
__device__ __forceinline__ uint32_t smem_u32(const void* p) {
    uint32_t a;
    asm("{ .reg .u64 t; cvta.to.shared.u64 t, %1; cvt.u32.u64 %0, t; }" : "=r"(a) : "l"(p));
    return a;
}
__device__ __forceinline__ void cp_async16(uint32_t sdst, const void* gsrc) {
    asm volatile("cp.async.cg.shared.global [%0], [%1], 16;" :: "r"(sdst), "l"(gsrc) : "memory");
}
__device__ __forceinline__ void cp_commit() {
    asm volatile("cp.async.commit_group;" ::: "memory");
}
__device__ __forceinline__ void ldm_x4(uint32_t addr, uint32_t& r0, uint32_t& r1,
                                       uint32_t& r2, uint32_t& r3) {
    asm volatile("ldmatrix.sync.aligned.m8n8.x4.shared.b16 {%0,%1,%2,%3}, [%4];"
                 : "=r"(r0), "=r"(r1), "=r"(r2), "=r"(r3) : "r"(addr));
}
__device__ __forceinline__ void ldm_x4_t(uint32_t addr, uint32_t& r0, uint32_t& r1,
                                         uint32_t& r2, uint32_t& r3) {
    asm volatile("ldmatrix.sync.aligned.m8n8.x4.trans.shared.b16 {%0,%1,%2,%3}, [%4];"
                 : "=r"(r0), "=r"(r1), "=r"(r2), "=r"(r3) : "r"(addr));
}
__device__ __forceinline__ void mma16816(float* c, const uint32_t* a, uint32_t b0, uint32_t b1) {
    asm volatile("mma.sync.aligned.m16n8k16.row.col.f32.f16.f16.f32 "
                 "{%0,%1,%2,%3}, {%4,%5,%6,%7}, {%8,%9}, {%0,%1,%2,%3};"
                 : "+f"(c[0]), "+f"(c[1]), "+f"(c[2]), "+f"(c[3])
                 : "r"(a[0]), "r"(a[1]), "r"(a[2]), "r"(a[3]), "r"(b0), "r"(b1));
}
__device__ __forceinline__ uint32_t pack_hf(f16 a, f16 b) {
    return (uint32_t)__half_as_ushort(a) | ((uint32_t)__half_as_ushort(b) << 16);
}

// ================= NT GEMM 128x128x64, pure fp16 =================
// SPLIT_OUT=0: fp32 C.  SPLIT_OUT=1: fp16 C (Chf).
template <int SPLIT_OUT>
__global__ __launch_bounds__(256, 2) void k_mma(
    const f16* __restrict__ A, long long lda,
    const f16* __restrict__ B, long long ldb,
    float* __restrict__ C, f16* __restrict__ Chf,
    long long ldc, int K, int Z2,
    long long sA1, long long sA2, long long sB1, long long sB2,
    long long sC1, long long sC2)
{
    extern __shared__ char smem[];
    const uint32_t sb = smem_u32(smem);
    const int tid = threadIdx.x;
    const int lane = tid & 31;
    const int warp = tid >> 5;
    const int wm = warp >> 2;
    const int wn = warp & 3;

    const int z = blockIdx.z, z1 = z / Z2, z2 = z % Z2;
    A += (long long)z1 * sA1 + (long long)z2 * sA2 + (long long)blockIdx.y * 128 * lda;
    B += (long long)z1 * sB1 + (long long)z2 * sB2 + (long long)blockIdx.x * 128 * ldb;
    const long long coff = (long long)z1 * sC1 + (long long)z2 * sC2
                         + (long long)blockIdx.y * 128 * ldc + (long long)blockIdx.x * 128;

    const int total = K / BK;

    float acc[4][4][4];
#pragma unroll
    for (int i = 0; i < 4; i++)
#pragma unroll
        for (int n = 0; n < 4; n++)
#pragma unroll
            for (int r = 0; r < 4; r++) acc[i][n][r] = 0.f;

    const int lrow = tid >> 3;
    const int lko  = tid & 7;

    auto issue_load = [&](int it) {
        const int kk = it * BK;
        const uint32_t sa = sb + (it % STAGES) * NST;
        const uint32_t sB = sa + NA_SZ;
#pragma unroll
        for (int q = 0; q < 4; q++) {
            const int row = lrow + q * 32;
            const uint32_t so = (uint32_t)row * NPITCH + lko * 16;
            cp_async16(sa + so, A + (size_t)row * lda + kk + lko * 8);
            cp_async16(sB + so, B + (size_t)row * ldb + kk + lko * 8);
        }
    };

#pragma unroll
    for (int s = 0; s < STAGES - 1; s++) {
        if (s < total) issue_load(s);
        cp_commit();
    }

    const uint32_t aRow = (uint32_t)(wm * 64 + (lane & 15));
    const uint32_t bRow = (uint32_t)(wn * 32 + (lane & 15));
    const uint32_t kByte = (uint32_t)((lane >> 4) * 16);

    for (int it = 0; it < total; ++it) {
        asm volatile("cp.async.wait_group %0;" :: "n"(STAGES - 2) : "memory");
        __syncthreads();
        const int nx = it + STAGES - 1;
        if (nx < total) issue_load(nx);
        cp_commit();

        const uint32_t sa = sb + (it % STAGES) * NST;
        const uint32_t sB = sa + NA_SZ;
#pragma unroll
        for (int k16 = 0; k16 < 4; k16++) {
            uint32_t a[4][4], b[2][4];
#pragma unroll
            for (int i = 0; i < 4; i++)
                ldm_x4(sa + (aRow + i * 16) * NPITCH + kByte + k16 * 32,
                       a[i][0], a[i][1], a[i][2], a[i][3]);
#pragma unroll
            for (int j = 0; j < 2; j++)
                ldm_x4(sB + (bRow + j * 16) * NPITCH + kByte + k16 * 32,
                       b[j][0], b[j][1], b[j][2], b[j][3]);
#pragma unroll
            for (int i = 0; i < 4; i++) {
#pragma unroll
                for (int n = 0; n < 4; n++) {
                    const int j = n >> 1, h = n & 1;
                    mma16816(acc[i][n], a[i], b[j][h], b[j][h + 2]);
                }
            }
        }
    }

    const int g = lane >> 2, t2 = (lane & 3) * 2;
#pragma unroll
    for (int i = 0; i < 4; i++) {
        const int r = wm * 64 + i * 16 + g;
#pragma unroll
        for (int n = 0; n < 4; n++) {
            const int cc = wn * 32 + (n >> 1) * 16 + (n & 1) * 8 + t2;
            if (SPLIT_OUT) {
                *(uint32_t*)(Chf + coff + (size_t)r * ldc + cc) =
                    pack_hf(__float2half_rn(acc[i][n][0]), __float2half_rn(acc[i][n][1]));
                *(uint32_t*)(Chf + coff + (size_t)(r + 8) * ldc + cc) =
                    pack_hf(__float2half_rn(acc[i][n][2]), __float2half_rn(acc[i][n][3]));
            } else {
                *(float2*)&C[coff + (size_t)r * ldc + cc]       = make_float2(acc[i][n][0], acc[i][n][1]);
                *(float2*)&C[coff + (size_t)(r + 8) * ldc + cc] = make_float2(acc[i][n][2], acc[i][n][3]);
            }
        }
    }
}

// ================= TN GEMM 128x128x64 (pure fp16): C[m,n] = sum_k A[k,m]*B[k,n] =================
__global__ __launch_bounds__(256, 2) void k_mma_tn(
    const f16* __restrict__ A, long long lda,
    const f16* __restrict__ B, long long ldb,
    float* __restrict__ C, long long ldc, int K, int Z2,
    long long sA1, long long sA2, long long sB1, long long sB2,
    long long sC1, long long sC2)
{
    extern __shared__ char smem[];
    const uint32_t sb = smem_u32(smem);
    const int tid = threadIdx.x;
    const int lane = tid & 31;
    const int warp = tid >> 5;
    const int wm = warp >> 2;
    const int wn = warp & 3;

    const int z = blockIdx.z, z1 = z / Z2, z2 = z % Z2;
    A += (long long)z1 * sA1 + (long long)z2 * sA2 + (long long)blockIdx.y * 128;
    B += (long long)z1 * sB1 + (long long)z2 * sB2 + (long long)blockIdx.x * 128;
    C += (long long)z1 * sC1 + (long long)z2 * sC2
       + (long long)blockIdx.y * 128 * ldc + (long long)blockIdx.x * 128;

    const int total = K / 64;

    float acc[4][4][4];
#pragma unroll
    for (int i = 0; i < 4; i++)
#pragma unroll
        for (int n = 0; n < 4; n++)
#pragma unroll
            for (int r = 0; r < 4; r++) acc[i][n][r] = 0.f;

    auto issue_load = [&](int it) {
        const int kk = it * 64;
        const uint32_t sa = sb + (it % STAGES) * ST_SZT;
        const uint32_t sB = sa + A_SZT;
#pragma unroll
        for (int q = 0; q < 4; q++) {
            const int c = tid + q * 256;
            const int row = c >> 4, col = c & 15;
            const uint32_t so = (uint32_t)row * ATP + col * 16;
            cp_async16(sa + so, A + (size_t)(kk + row) * lda + col * 8);
            cp_async16(sB + so, B + (size_t)(kk + row) * ldb + col * 8);
        }
    };

#pragma unroll
    for (int s = 0; s < STAGES - 1; s++) {
        if (s < total) issue_load(s);
        cp_commit();
    }

    const uint32_t aK = (lane & 7) + ((lane >> 4) & 1) * 8;
    const uint32_t aM = (uint32_t)(wm * 64) * 2 + ((lane >> 3) & 1) * 16;
    const uint32_t bK = (lane & 7) + ((lane >> 3) & 1) * 8;
    const uint32_t bN = (uint32_t)(wn * 32) * 2 + ((lane >> 4) & 1) * 16;

    for (int it = 0; it < total; ++it) {
        asm volatile("cp.async.wait_group %0;" :: "n"(STAGES - 2) : "memory");
        __syncthreads();
        const int nx = it + STAGES - 1;
        if (nx < total) issue_load(nx);
        cp_commit();

        const uint32_t sa = sb + (it % STAGES) * ST_SZT;
        const uint32_t sB = sa + A_SZT;
#pragma unroll
        for (int k16 = 0; k16 < 4; k16++) {
            uint32_t a[4][4], b[2][4];
#pragma unroll
            for (int i = 0; i < 4; i++)
                ldm_x4_t(sa + (k16 * 16 + aK) * ATP + aM + i * 32,
                         a[i][0], a[i][1], a[i][2], a[i][3]);
#pragma unroll
            for (int gidx = 0; gidx < 2; gidx++)
                ldm_x4_t(sB + (k16 * 16 + bK) * ATP + bN + gidx * 32,
                         b[gidx][0], b[gidx][1], b[gidx][2], b[gidx][3]);
#pragma unroll
            for (int i = 0; i < 4; i++) {
#pragma unroll
                for (int n = 0; n < 4; n++) {
                    const int gr = n >> 1, h = (n & 1) * 2;
                    mma16816(acc[i][n], a[i], b[gr][h], b[gr][h + 1]);
                }
            }
        }
    }

    const int g = lane >> 2, t2 = (lane & 3) * 2;
#pragma unroll
    for (int i = 0; i < 4; i++) {
        const int r = wm * 64 + i * 16 + g;
#pragma unroll
        for (int n = 0; n < 4; n++) {
            const int cc = wn * 32 + (n >> 1) * 16 + (n & 1) * 8 + t2;
            *(float2*)&C[(size_t)r * ldc + cc]       = make_float2(acc[i][n][0], acc[i][n][1]);
            *(float2*)&C[(size_t)(r + 8) * ldc + cc] = make_float2(acc[i][n][2], acc[i][n][3]);
        }
    }
}

// ================= fused G1 + SwiGLU (pure fp16, 128 rows x 64 f-cols) =================
__global__ __launch_bounds__(256, 2) void k_mma_swiglu(
    const f16* __restrict__ A, const f16* __restrict__ B, f16* __restrict__ H)
{
    extern __shared__ char smem[];
    const uint32_t sb = smem_u32(smem);
    const int tid = threadIdx.x;
    const int lane = tid & 31;
    const int warp = tid >> 5;
    const int wm = warp >> 2;
    const int wn = warp & 3;

    int l = blockIdx.y * gridDim.x + blockIdx.x;
    const int per = 8 * gridDim.x;
    const int grp = l / per, rem = l % per;
    const int by = grp * 8 + (rem & 7);
    const int bx = rem >> 3;

    const int total = 16;   // K=1024/64, 1-term

    float accg[4][2][4], accu[4][2][4];
#pragma unroll
    for (int i = 0; i < 4; i++)
#pragma unroll
        for (int n = 0; n < 2; n++)
#pragma unroll
            for (int r = 0; r < 4; r++) { accg[i][n][r] = 0.f; accu[i][n][r] = 0.f; }

    const int lrow = tid >> 3;
    const int lko  = tid & 7;

    auto issue_load = [&](int it) {
        const int kk = it * BK;
        const uint32_t sa = sb + (it % STAGES) * NST;
        const uint32_t sB = sa + NA_SZ;
#pragma unroll
        for (int q = 0; q < 4; q++) {
            const int row = lrow + q * 32;
            const uint32_t so = (uint32_t)row * NPITCH + lko * 16;
            cp_async16(sa + so, A + (size_t)(by * 128 + row) * 1024 + kk + lko * 8);
            const size_t grow = (row < 64) ? (size_t)(bx * 64 + row)
                                           : (size_t)(4096 + bx * 64 + row - 64);
            cp_async16(sB + so, B + grow * 1024 + kk + lko * 8);
        }
    };

#pragma unroll
    for (int s = 0; s < STAGES - 1; s++) { issue_load(s); cp_commit(); }

    const uint32_t aRow = (uint32_t)(wm * 64 + (lane & 15));
    const uint32_t gRow = (uint32_t)(wn * 16 + (lane & 15));
    const uint32_t uRow = gRow + 64;
    const uint32_t kByte = (uint32_t)((lane >> 4) * 16);

    for (int it = 0; it < total; ++it) {
        asm volatile("cp.async.wait_group %0;" :: "n"(STAGES - 2) : "memory");
        __syncthreads();
        const int nx = it + STAGES - 1;
        if (nx < total) issue_load(nx);
        cp_commit();

        const uint32_t sa = sb + (it % STAGES) * NST;
        const uint32_t sB = sa + NA_SZ;
#pragma unroll
        for (int k16 = 0; k16 < 4; k16++) {
            uint32_t a[4][4], bg[4], bu[4];
#pragma unroll
            for (int i = 0; i < 4; i++)
                ldm_x4(sa + (aRow + i * 16) * NPITCH + kByte + k16 * 32,
                       a[i][0], a[i][1], a[i][2], a[i][3]);
            ldm_x4(sB + gRow * NPITCH + kByte + k16 * 32, bg[0], bg[1], bg[2], bg[3]);
            ldm_x4(sB + uRow * NPITCH + kByte + k16 * 32, bu[0], bu[1], bu[2], bu[3]);
#pragma unroll
            for (int i = 0; i < 4; i++) {
#pragma unroll
                for (int n = 0; n < 2; n++) {
                    mma16816(accg[i][n], a[i], bg[n], bg[n + 2]);
                    mma16816(accu[i][n], a[i], bu[n], bu[n + 2]);
                }
            }
        }
    }

    const int g = lane >> 2, t2 = (lane & 3) * 2;
#pragma unroll
    for (int i = 0; i < 4; i++) {
#pragma unroll
        for (int n = 0; n < 2; n++) {
            const int col = bx * 64 + wn * 16 + n * 8 + t2;
#pragma unroll
            for (int half = 0; half < 2; half++) {
                const size_t row = (size_t)by * 128 + wm * 64 + i * 16 + g + half * 8;
                float g0 = accg[i][n][half * 2 + 0], g1 = accg[i][n][half * 2 + 1];
                float u0 = accu[i][n][half * 2 + 0], u1 = accu[i][n][half * 2 + 1];
                float h0 = g0 / (1.0f + expf(-g0)) * u0;
                float h1 = g1 / (1.0f + expf(-g1)) * u1;
                *(uint32_t*)(H + row * 4096 + col) =
                    pack_hf(__float2half_rn(h0), __float2half_rn(h1));
            }
        }
    }
}

// ================= elementwise kernels =================
__global__ void k_convert4(const float* __restrict__ in, f16* __restrict__ hi, long long n)
{
    long long i = ((long long)blockIdx.x * blockDim.x + threadIdx.x) * 4;
    if (i >= n) return;
    float4 v = *(const float4*)(in + i);
    *(uint2*)(hi + i) = make_uint2(
        pack_hf(__float2half_rn(v.x), __float2half_rn(v.y)),
        pack_hf(__float2half_rn(v.z), __float2half_rn(v.w)));
}

__global__ void k_conv_split4(const float* __restrict__ tt, const float* __restrict__ cw,
                              const float* __restrict__ cb, f16* __restrict__ thi)
{
    long long idx = (long long)blockIdx.x * blockDim.x + threadIdx.x;
    if (idx >= (long long)2 * 4096 * 256) return;
    int d4 = (int)(idx & 255) * 4;
    long long bi = idx >> 8;
    int i = (int)(bi & 4095);
    int b = (int)(bi >> 12);
    const float* base = tt + (long long)b * 4096 * 1024 + d4;
    float4 acc = *(const float4*)(cb + d4);
#pragma unroll
    for (int k = 0; k < KSIZE; k++) {
        int src = i - (KSIZE - 1) + k;
        if (src >= 0) {
            float4 v = *(const float4*)(base + (long long)src * 1024);
            acc.x += v.x * cw[(d4 + 0) * KSIZE + k];
            acc.y += v.y * cw[(d4 + 1) * KSIZE + k];
            acc.z += v.z * cw[(d4 + 2) * KSIZE + k];
            acc.w += v.w * cw[(d4 + 3) * KSIZE + k];
        }
    }
    size_t o = ((size_t)b * 4096 + i) * 1024 + d4;
    *(uint2*)(thi + o) = make_uint2(
        pack_hf(__float2half_rn(acc.x), __float2half_rn(acc.y)),
        pack_hf(__float2half_rn(acc.z), __float2half_rn(acc.w)));
}

// per-batch cumsum of dd -> wa (fp16, hi only); pointers pre-offset by batch
__global__ void k_wadp4b(const float* __restrict__ dd, const float* __restrict__ wdown,
                         f16* __restrict__ w)
{
    long long i = ((long long)blockIdx.x * blockDim.x + threadIdx.x) * 4;
    const long long DF = 1LL << 22;
    if (i >= DF) return;
    float4 acc = *(const float4*)(wdown + i);
#pragma unroll
    for (int j = 0; j < 16; j++) {
        size_t o = ((size_t)j << 22) + i;
        *(uint2*)(w + o) = make_uint2(
            pack_hf(__float2half_rn(acc.x), __float2half_rn(acc.y)),
            pack_hf(__float2half_rn(acc.z), __float2half_rn(acc.w)));
        if (j < 15) {
            float4 d4 = *(const float4*)(dd + ((size_t)j << 22) + i);
            acc.x += TTT_LR * d4.x; acc.y += TTT_LR * d4.y;
            acc.z += TTT_LR * d4.z; acc.w += TTT_LR * d4.w;
        }
    }
}

// per-batch reduce of 2 split-K partials
__global__ void k_reduce2b(const float* __restrict__ p0, const float* __restrict__ p1,
                           float* __restrict__ out)
{
    const long long N = 1LL << 22;
    long long i = ((long long)blockIdx.x * blockDim.x + threadIdx.x) * 4;
    if (i >= N) return;
    float4 a = *(const float4*)(p0 + i);
    float4 b = *(const float4*)(p1 + i);
    *(float4*)(out + i) = make_float4(a.x + b.x, a.y + b.y, a.z + b.z, a.w + b.w);
}

// ================= launch =================
extern "C" void kernel_launch(void* const* d_in, const int* in_sizes, int n_in,
                              void* d_out, int out_size)
{
    const float* x     = (const float*)d_in[0];
    const float* tt    = (const float*)d_in[1];
    const float* wgu   = (const float*)d_in[2];
    const float* wdown = (const float*)d_in[3];
    const float* proj  = (const float*)d_in[4];
    const float* cw    = (const float*)d_in[5];
    const float* cb    = (const float*)d_in[6];
    float* out = (float*)d_out;

    f16 *hv, *xv, *wguv, *projv, *tv, *tpv, *wav;
    float *dd, *p4;
    cudaGetSymbolAddress((void**)&hv, g_h);
    cudaGetSymbolAddress((void**)&xv, g_x);
    cudaGetSymbolAddress((void**)&wguv, g_wgu);
    cudaGetSymbolAddress((void**)&projv, g_proj);
    cudaGetSymbolAddress((void**)&tv, g_t);
    cudaGetSymbolAddress((void**)&tpv, g_tp);
    cudaGetSymbolAddress((void**)&wav, g_wa);
    cudaGetSymbolAddress((void**)&dd, g_dd);
    cudaGetSymbolAddress((void**)&p4, g_p4);

    static bool s_init = false;
    static cudaStream_t s1, s2;
    static cudaEvent_t evFork, evWgu, evSide, evW0, evW1, evG40, evR0;
    if (!s_init) {
        s_init = true;
        cudaStreamCreateWithFlags(&s1, cudaStreamNonBlocking);
        cudaStreamCreateWithFlags(&s2, cudaStreamNonBlocking);
        cudaEventCreateWithFlags(&evFork, cudaEventDisableTiming);
        cudaEventCreateWithFlags(&evWgu,  cudaEventDisableTiming);
        cudaEventCreateWithFlags(&evSide, cudaEventDisableTiming);
        cudaEventCreateWithFlags(&evW0,   cudaEventDisableTiming);
        cudaEventCreateWithFlags(&evW1,   cudaEventDisableTiming);
        cudaEventCreateWithFlags(&evG40,  cudaEventDisableTiming);
        cudaEventCreateWithFlags(&evR0,   cudaEventDisableTiming);
        cudaFuncSetAttribute(k_mma<0>, cudaFuncAttributeMaxDynamicSharedMemorySize, SMEM_NT);
        cudaFuncSetAttribute(k_mma<1>, cudaFuncAttributeMaxDynamicSharedMemorySize, SMEM_NT);
        cudaFuncSetAttribute(k_mma_tn, cudaFuncAttributeMaxDynamicSharedMemorySize, SMEM_TN);
        cudaFuncSetAttribute(k_mma_swiglu, cudaFuncAttributeMaxDynamicSharedMemorySize, SMEM_NT);
    }

    const long long DF   = 1LL << 22;             // 1024*4096
    const long long HB   = 4096LL * 4096;         // h batch stride
    const long long WAB  = 16LL * DF;             // wa batch stride
    const long long PB   = DF;                    // p4 batch stride
    const long long PS   = 2LL * DF;              // p4 split stride

    // fork
    cudaEventRecord(evFork, 0);
    cudaStreamWaitEvent(s1, evFork, 0);
    cudaStreamWaitEvent(s2, evFork, 0);

    // s2: wgu convert (feeds G1)
    k_convert4<<<(int)((8192LL * 1024 / 4 + 255) / 256), 256, 0, s2>>>(
        wgu, wguv, 8192LL * 1024);
    cudaEventRecord(evWgu, s2);

    // s1: conv -> proj convert -> G2 (pure fp16)
    k_conv_split4<<<(int)((2LL * 4096 * 256 + 255) / 256), 256, 0, s1>>>(tt, cw, cb, tv);
    k_convert4<<<(int)((1024LL * 1024 / 4 + 255) / 256), 256, 0, s1>>>(
        proj, projv, 1024LL * 1024);
    k_mma<1><<<dim3(8, 30, 2), 256, SMEM_NT, s1>>>(
        tv, 1024, projv, 1024,
        nullptr, tpv, 1024, 1024, 1,
        4096LL * 1024, 0, 0, 0, 3840LL * 1024, 0);
    cudaEventRecord(evSide, s1);

    // null: x convert -> (join wgu) -> G1+SwiGLU (pure fp16)
    k_convert4<<<(int)((8192LL * 1024 / 4 + 255) / 256), 256>>>(x, xv, 8192LL * 1024);
    cudaStreamWaitEvent(0, evWgu, 0);
    k_mma_swiglu<<<dim3(64, 64, 1), 256, SMEM_NT>>>(xv, wguv, hv);

    // join side chain before G3
    cudaStreamWaitEvent(0, evSide, 0);

    // G3 (TN, pure fp16), full-width z=30
    k_mma_tn<<<dim3(32, 8, 30), 256, SMEM_TN>>>(
        tpv, 1024, hv, 4096, dd, 4096, 256, 15,
        3840LL * 1024, 256LL * 1024, 4096LL * 4096, 256LL * 4096,
        15LL * 1024 * 4096, 1024LL * 4096);

    // wadp batch 0 (null), then fork: G4(b0) on null || wadp batch 1 on s1
    k_wadp4b<<<(int)((DF / 4 + 255) / 256), 256>>>(dd, wdown, wav);
    cudaEventRecord(evW0, 0);
    cudaStreamWaitEvent(s1, evW0, 0);
    k_wadp4b<<<(int)((DF / 4 + 255) / 256), 256, 0, s1>>>(
        dd + 15 * DF, wdown, wav + WAB);
    cudaEventRecord(evW1, s1);

    // G4 batch 0 (split-K=2, pure fp16)
    k_mma<0><<<dim3(8, 2, 32), 256, SMEM_NT>>>(
        hv, 4096, wav, 4096,
        p4, nullptr, 1024, 2048, 2,
        256LL * 4096, 2048, DF, 2048,
        256LL * 1024, PS);
    cudaEventRecord(evG40, 0);

    // reduce(b0) on s2 concurrent with G4(b1)
    cudaStreamWaitEvent(s2, evG40, 0);
    k_reduce2b<<<(int)((DF / 4 + 255) / 256), 256, 0, s2>>>(p4, p4 + PS, out);
    cudaEventRecord(evR0, s2);

    // G4 batch 1 after wadp(b1)
    cudaStreamWaitEvent(0, evW1, 0);
    k_mma<0><<<dim3(8, 2, 32), 256, SMEM_NT>>>(
        hv + HB, 4096, wav + WAB, 4096,
        p4 + PB, nullptr, 1024, 2048, 2,
        256LL * 4096, 2048, DF, 2048,
        256LL * 1024, PS);

    // reduce(b1) on null, then join reduce(b0)
    k_reduce2b<<<(int)((DF / 4 + 255) / 256), 256>>>(p4 + PB, p4 + PS + PB, out + DF);
    cudaStreamWaitEvent(0, evR0, 0);
}